// round 4
// baseline (speedup 1.0000x reference)
#include <cuda_runtime.h>

#define NN 1024
#define BB 8
#define DIN 64
#define DOUT 64
#define EMB 16
#define DPE 16
#define KIO 8192   // 2*64*64

// ---- device scratch (no allocations allowed) ----
__device__ float g_sim[NN * NN];          // 4 MB
__device__ float g_w[NN * KIO];           // 32 MB  weights[n][k][i][o]
__device__ float g_bias[NN * DOUT];       // 256 KB
__device__ float g_e[BB * NN * NN];       // 32 MB  exp(-d1), symmetric per b
__device__ float g_Sinv[BB * NN];         // 32 KB
__device__ float g_sxT[NN * BB * DIN];    // 2 MB   sx as [m][b][d]
__device__ float g_s1[NN * BB * DIN];     // 2 MB   sim@sx as [n][b][d]

// ---------------------------------------------------------------------------
// K0: sim = softmax(relu(E E^T), axis=1)   one block per row
// ---------------------------------------------------------------------------
__global__ __launch_bounds__(256) void sim_kernel(const float* __restrict__ E) {
    const int i = blockIdx.x;
    const int t = threadIdx.x;
    __shared__ float Ei[EMB];
    __shared__ float red[256];
    if (t < EMB) Ei[t] = E[i * EMB + t];
    __syncthreads();

    float v[4];
    float mx = -1e30f;
#pragma unroll
    for (int r = 0; r < 4; r++) {
        int j = t + r * 256;
        const float4* Ej = reinterpret_cast<const float4*>(E + j * EMB);
        float acc = 0.f;
#pragma unroll
        for (int q = 0; q < 4; q++) {
            float4 e4 = Ej[q];
            acc += Ei[q * 4 + 0] * e4.x + Ei[q * 4 + 1] * e4.y
                 + Ei[q * 4 + 2] * e4.z + Ei[q * 4 + 3] * e4.w;
        }
        acc = fmaxf(acc, 0.f);
        v[r] = acc;
        mx = fmaxf(mx, acc);
    }
    red[t] = mx; __syncthreads();
    for (int s = 128; s > 0; s >>= 1) { if (t < s) red[t] = fmaxf(red[t], red[t + s]); __syncthreads(); }
    mx = red[0]; __syncthreads();

    float sum = 0.f;
#pragma unroll
    for (int r = 0; r < 4; r++) { v[r] = __expf(v[r] - mx); sum += v[r]; }
    red[t] = sum; __syncthreads();
    for (int s = 128; s > 0; s >>= 1) { if (t < s) red[t] += red[t + s]; __syncthreads(); }
    float inv = 1.0f / red[0];
#pragma unroll
    for (int r = 0; r < 4; r++) g_sim[i * NN + t + r * 256] = v[r] * inv;
}

// ---------------------------------------------------------------------------
// K1: weights[n, kio] = sum_d E[n,d] * Wp[d, kio]
// grid (32 kio-tiles of 256, 8 n-chunks of 128)
// ---------------------------------------------------------------------------
__global__ __launch_bounds__(256) void weights_kernel(const float* __restrict__ E,
                                                      const float* __restrict__ Wp) {
    const int t = threadIdx.x;
    const int kio = blockIdx.x * 256 + t;
    const int n0 = blockIdx.y * 128;
    __shared__ float Ws[EMB][256];
    __shared__ float Es[128][EMB];
#pragma unroll
    for (int d = 0; d < EMB; d++) Ws[d][t] = Wp[d * KIO + kio];
    for (int idx = t; idx < 128 * EMB; idx += 256)
        Es[idx >> 4][idx & 15] = E[(n0 + (idx >> 4)) * EMB + (idx & 15)];
    __syncthreads();
    for (int nn = 0; nn < 128; nn++) {
        float acc = 0.f;
#pragma unroll
        for (int d = 0; d < EMB; d++) acc += Es[nn][d] * Ws[d][t];
        g_w[(size_t)(n0 + nn) * KIO + kio] = acc;
    }
}

// K1b: bias[n,o] = sum_d E[n,d] * bp[d,o]
__global__ __launch_bounds__(256) void bias_kernel(const float* __restrict__ E,
                                                   const float* __restrict__ bp) {
    int idx = blockIdx.x * 256 + threadIdx.x;       // 65536
    int n = idx >> 6, o = idx & 63;
    float acc = 0.f;
#pragma unroll
    for (int d = 0; d < EMB; d++) acc += E[n * EMB + d] * bp[d * DOUT + o];
    g_bias[idx] = acc;
}

// ---------------------------------------------------------------------------
// K2: e[b,i,j] = exp(-sum_d |pa[b,i,d]-pa[b,j,d]|)
// grid (16 j-tiles of 64, 8 i-tiles of 128, 8 b)
// ---------------------------------------------------------------------------
__global__ __launch_bounds__(256) void e_kernel(const float* __restrict__ pa) {
    const int b = blockIdx.z;
    const int i0 = blockIdx.y * 128;
    const int j0 = blockIdx.x * 64;
    const int t = threadIdx.x;
    __shared__ float paI[128][17];
    __shared__ float paJ[64][17];
    const float* paB = pa + (size_t)b * NN * DPE;
    for (int idx = t; idx < 128 * 16; idx += 256)
        paI[idx >> 4][idx & 15] = paB[(i0 + (idx >> 4)) * DPE + (idx & 15)];
    for (int idx = t; idx < 64 * 16; idx += 256)
        paJ[idx >> 4][idx & 15] = paB[(j0 + (idx >> 4)) * DPE + (idx & 15)];
    __syncthreads();

    const int tj = t & 63, tig = t >> 6;
    float pj[16];
#pragma unroll
    for (int d = 0; d < 16; d++) pj[d] = paJ[tj][d];

    float* outBase = g_e + ((size_t)b * NN + i0) * NN + j0;
    for (int s = 0; s < 32; s++) {
        int i = tig * 32 + s;
        float acc = 0.f;
#pragma unroll
        for (int d = 0; d < 16; d++) acc += fabsf(paI[i][d] - pj[d]);
        outBase[(size_t)i * NN + tj] = __expf(-acc);
    }
}

// K3: Sinv[b,i] = 1 / sum_j e[b,i,j]   (row sum == column sum by symmetry)
__global__ __launch_bounds__(256) void rowsum_kernel() {
    int row = blockIdx.x * 8 + (threadIdx.x >> 5);   // 8192 rows
    int lane = threadIdx.x & 31;
    const float* r = g_e + (size_t)row * NN;
    float s = 0.f;
    for (int j = lane; j < NN; j += 32) s += r[j];
#pragma unroll
    for (int o = 16; o > 0; o >>= 1) s += __shfl_xor_sync(0xffffffffu, s, o);
    if (lane == 0) g_Sinv[row] = 1.0f / s;
}

// ---------------------------------------------------------------------------
// K4: sxT[m][b][d] = sum_c e[b,m,c] * (x[b,c,d] * Sinv[b,c])
// 64x64 tile GEMM, K-step 32.  grid (16 m-tiles, 8 b)
// ---------------------------------------------------------------------------
__global__ __launch_bounds__(256) void sx_kernel(const float* __restrict__ x) {
    const int b = blockIdx.y, m0 = blockIdx.x * 64;
    const int t = threadIdx.x;
    const int tm = t >> 4, td = t & 15;
    __shared__ float aS[64][33];
    __shared__ float bS[32][64];
    float acc[4][4] = {};
    const float* eB = g_e + ((size_t)b * NN + m0) * NN;
    const float* xB = x + (size_t)b * NN * DIN;
    const float* sI = g_Sinv + b * NN;

    for (int c0 = 0; c0 < NN; c0 += 32) {
        __syncthreads();
#pragma unroll
        for (int l = 0; l < 8; l++) {
            int idx = t + l * 256;
            int r = idx >> 5, c = idx & 31;
            aS[r][c] = eB[(size_t)r * NN + c0 + c];
        }
#pragma unroll
        for (int l = 0; l < 8; l++) {
            int idx = t + l * 256;
            int r = idx >> 6, d = idx & 63;
            bS[r][d] = xB[(c0 + r) * DIN + d] * sI[c0 + r];
        }
        __syncthreads();
#pragma unroll 8
        for (int kk = 0; kk < 32; kk++) {
            float a0 = aS[tm * 4 + 0][kk], a1 = aS[tm * 4 + 1][kk];
            float a2 = aS[tm * 4 + 2][kk], a3 = aS[tm * 4 + 3][kk];
            float4 bv = *reinterpret_cast<const float4*>(&bS[kk][td * 4]);
            acc[0][0] += a0 * bv.x; acc[0][1] += a0 * bv.y; acc[0][2] += a0 * bv.z; acc[0][3] += a0 * bv.w;
            acc[1][0] += a1 * bv.x; acc[1][1] += a1 * bv.y; acc[1][2] += a1 * bv.z; acc[1][3] += a1 * bv.w;
            acc[2][0] += a2 * bv.x; acc[2][1] += a2 * bv.y; acc[2][2] += a2 * bv.z; acc[2][3] += a2 * bv.w;
            acc[3][0] += a3 * bv.x; acc[3][1] += a3 * bv.y; acc[3][2] += a3 * bv.z; acc[3][3] += a3 * bv.w;
        }
    }
#pragma unroll
    for (int mi = 0; mi < 4; mi++) {
        float4 v = make_float4(acc[mi][0], acc[mi][1], acc[mi][2], acc[mi][3]);
        *reinterpret_cast<float4*>(&g_sxT[((size_t)(m0 + tm * 4 + mi) * BB + b) * DIN + td * 4]) = v;
    }
}

// ---------------------------------------------------------------------------
// K5: s1[n][bd] = sum_m sim[n,m] * sxT[m][bd]   (single 1024x512x1024 GEMM)
// grid (16 n-tiles, 8 bd-tiles)
// ---------------------------------------------------------------------------
__global__ __launch_bounds__(256) void s1_kernel() {
    const int n0 = blockIdx.x * 64, bd0 = blockIdx.y * 64;
    const int t = threadIdx.x;
    const int tm = t >> 4, td = t & 15;
    __shared__ float aS[64][33];
    __shared__ float bS[32][64];
    float acc[4][4] = {};

    for (int c0 = 0; c0 < NN; c0 += 32) {
        __syncthreads();
#pragma unroll
        for (int l = 0; l < 8; l++) {
            int idx = t + l * 256;
            int r = idx >> 5, c = idx & 31;
            aS[r][c] = g_sim[(size_t)(n0 + r) * NN + c0 + c];
        }
#pragma unroll
        for (int l = 0; l < 8; l++) {
            int idx = t + l * 256;
            int r = idx >> 6, d = idx & 63;
            bS[r][d] = g_sxT[(size_t)(c0 + r) * (BB * DIN) + bd0 + d];
        }
        __syncthreads();
#pragma unroll 8
        for (int kk = 0; kk < 32; kk++) {
            float a0 = aS[tm * 4 + 0][kk], a1 = aS[tm * 4 + 1][kk];
            float a2 = aS[tm * 4 + 2][kk], a3 = aS[tm * 4 + 3][kk];
            float4 bv = *reinterpret_cast<const float4*>(&bS[kk][td * 4]);
            acc[0][0] += a0 * bv.x; acc[0][1] += a0 * bv.y; acc[0][2] += a0 * bv.z; acc[0][3] += a0 * bv.w;
            acc[1][0] += a1 * bv.x; acc[1][1] += a1 * bv.y; acc[1][2] += a1 * bv.z; acc[1][3] += a1 * bv.w;
            acc[2][0] += a2 * bv.x; acc[2][1] += a2 * bv.y; acc[2][2] += a2 * bv.z; acc[2][3] += a2 * bv.w;
            acc[3][0] += a3 * bv.x; acc[3][1] += a3 * bv.y; acc[3][2] += a3 * bv.z; acc[3][3] += a3 * bv.w;
        }
    }
#pragma unroll
    for (int mi = 0; mi < 4; mi++) {
        float4 v = make_float4(acc[mi][0], acc[mi][1], acc[mi][2], acc[mi][3]);
        *reinterpret_cast<float4*>(&g_s1[(size_t)(n0 + tm * 4 + mi) * (BB * DIN) + bd0 + td * 4]) = v;
    }
}

// ---------------------------------------------------------------------------
// K6: out[b,n,o] = bias[n,o] + sum_i sx[n,b,i] w[n,0,i,o] + sum_i s1[n,b,i] w[n,1,i,o]
// one block per n; weights tile resident in smem
// ---------------------------------------------------------------------------
__global__ __launch_bounds__(256) void out_kernel(float* __restrict__ out) {
    const int n = blockIdx.x, t = threadIdx.x;
    __shared__ float wS[KIO];          // 32 KB
    __shared__ float xgS[2][BB][DIN];  // 4 KB
    __shared__ float bS[DOUT];
    const float* wp = g_w + (size_t)n * KIO;
    for (int idx = t; idx < KIO; idx += 256) wS[idx] = wp[idx];
    for (int idx = t; idx < BB * DIN; idx += 256) {
        xgS[0][idx >> 6][idx & 63] = g_sxT[(size_t)n * (BB * DIN) + idx];
        xgS[1][idx >> 6][idx & 63] = g_s1[(size_t)n * (BB * DIN) + idx];
    }
    if (t < DOUT) bS[t] = g_bias[n * DOUT + t];
    __syncthreads();

#pragma unroll
    for (int r = 0; r < 2; r++) {
        int idx = t + r * 256;
        int b = idx >> 6, o = idx & 63;
        float acc = bS[o];
#pragma unroll
        for (int i = 0; i < DIN; i++) acc += xgS[0][b][i] * wS[i * 64 + o];
#pragma unroll
        for (int i = 0; i < DIN; i++) acc += xgS[1][b][i] * wS[4096 + i * 64 + o];
        out[((size_t)b * NN + n) * DOUT + o] = acc;
    }
}

// ---------------------------------------------------------------------------
extern "C" void kernel_launch(void* const* d_in, const int* in_sizes, int n_in,
                              void* d_out, int out_size) {
    const float* x    = (const float*)d_in[0];   // [8,1024,64]
    const float* E    = (const float*)d_in[1];   // [1024,16]
    const float* pa   = (const float*)d_in[2];   // [8,1024,16]
    const float* Wp   = (const float*)d_in[3];   // [16,2,64,64]
    const float* bp   = (const float*)d_in[4];   // [16,64]
    float* out = (float*)d_out;                  // [8,1024,64]

    sim_kernel<<<NN, 256>>>(E);
    weights_kernel<<<dim3(KIO / 256, NN / 128), 256>>>(E, Wp);
    bias_kernel<<<NN * DOUT / 256, 256>>>(E, bp);
    e_kernel<<<dim3(NN / 64, NN / 128, BB), 256>>>(pa);
    rowsum_kernel<<<BB * NN / 8, 256>>>();
    sx_kernel<<<dim3(NN / 64, BB), 256>>>(x);
    s1_kernel<<<dim3(NN / 64, BB * DIN / 64), 256>>>();
    out_kernel<<<NN, 256>>>(out);
}

// round 5
// speedup vs baseline: 1.1692x; 1.1692x over previous
#include <cuda_runtime.h>

#define NN 1024
#define BB 8
#define DIN 64
#define DOUT 64
#define EMB 16
#define DPE 16
#define KIO 8192   // 2*64*64

// ---- device scratch (no allocations allowed) ----
__device__ float g_sim[NN * NN];          // 4 MB
__device__ float g_w[NN * KIO];           // 32 MB  weights[n][k][i][o]
__device__ float g_bias[NN * DOUT];       // 256 KB
__device__ float g_e[BB * NN * NN];       // 32 MB  exp(-d1), symmetric per b
__device__ float g_Sinv[BB * NN];         // 32 KB
__device__ float g_sxT[NN * BB * DIN];    // 2 MB   sx as [m][b][d]
__device__ float g_s1[NN * BB * DIN];     // 2 MB   sim@sx as [n][b][d]

// ---------------------------------------------------------------------------
// K0: sim = softmax(relu(E E^T), axis=1)   one block per row
// ---------------------------------------------------------------------------
__global__ __launch_bounds__(256) void sim_kernel(const float* __restrict__ E) {
    const int i = blockIdx.x;
    const int t = threadIdx.x;
    __shared__ float Ei[EMB];
    __shared__ float red[256];
    if (t < EMB) Ei[t] = E[i * EMB + t];
    __syncthreads();

    float v[4];
    float mx = -1e30f;
#pragma unroll
    for (int r = 0; r < 4; r++) {
        int j = t + r * 256;
        const float4* Ej = reinterpret_cast<const float4*>(E + j * EMB);
        float acc = 0.f;
#pragma unroll
        for (int q = 0; q < 4; q++) {
            float4 e4 = Ej[q];
            acc += Ei[q * 4 + 0] * e4.x + Ei[q * 4 + 1] * e4.y
                 + Ei[q * 4 + 2] * e4.z + Ei[q * 4 + 3] * e4.w;
        }
        acc = fmaxf(acc, 0.f);
        v[r] = acc;
        mx = fmaxf(mx, acc);
    }
    red[t] = mx; __syncthreads();
    for (int s = 128; s > 0; s >>= 1) { if (t < s) red[t] = fmaxf(red[t], red[t + s]); __syncthreads(); }
    mx = red[0]; __syncthreads();

    float sum = 0.f;
#pragma unroll
    for (int r = 0; r < 4; r++) { v[r] = __expf(v[r] - mx); sum += v[r]; }
    red[t] = sum; __syncthreads();
    for (int s = 128; s > 0; s >>= 1) { if (t < s) red[t] += red[t + s]; __syncthreads(); }
    float inv = 1.0f / red[0];
#pragma unroll
    for (int r = 0; r < 4; r++) g_sim[i * NN + t + r * 256] = v[r] * inv;
}

// ---------------------------------------------------------------------------
// K1: weights[n, kio] = sum_d E[n,d] * Wp[d, kio]
// Wp column held in 16 registers; E rows via broadcast LDS.128.
// grid (KIO/256, NN/128)
// ---------------------------------------------------------------------------
__global__ __launch_bounds__(256) void weights_kernel(const float* __restrict__ E,
                                                      const float* __restrict__ Wp) {
    const int t = threadIdx.x;
    const int kio = blockIdx.x * 256 + t;
    const int n0 = blockIdx.y * 128;

    float w[EMB];
#pragma unroll
    for (int d = 0; d < EMB; d++) w[d] = Wp[d * KIO + kio];   // coalesced

    __shared__ float Es[128][20];   // padded: rows 20 floats, 16B-aligned
#pragma unroll
    for (int l = 0; l < 2; l++) {
        int idx4 = t + l * 256;                 // 512 float4s
        int r = idx4 >> 2, q4 = (idx4 & 3) * 4;
        *reinterpret_cast<float4*>(&Es[r][q4]) =
            *reinterpret_cast<const float4*>(&E[(n0 + r) * EMB + q4]);
    }
    __syncthreads();

    float* outp = g_w + (size_t)n0 * KIO + kio;
#pragma unroll 4
    for (int nn = 0; nn < 128; nn++) {
        float4 e0 = *reinterpret_cast<const float4*>(&Es[nn][0]);
        float4 e1 = *reinterpret_cast<const float4*>(&Es[nn][4]);
        float4 e2 = *reinterpret_cast<const float4*>(&Es[nn][8]);
        float4 e3 = *reinterpret_cast<const float4*>(&Es[nn][12]);
        float a0 = e0.x * w[0] + e0.y * w[1] + e0.z * w[2] + e0.w * w[3]
                 + e1.x * w[4] + e1.y * w[5] + e1.z * w[6] + e1.w * w[7];
        float a1 = e2.x * w[8] + e2.y * w[9] + e2.z * w[10] + e2.w * w[11]
                 + e3.x * w[12] + e3.y * w[13] + e3.z * w[14] + e3.w * w[15];
        outp[(size_t)nn * KIO] = a0 + a1;
    }
}

// K1b: bias[n,o] = sum_d E[n,d] * bp[d,o]
__global__ __launch_bounds__(256) void bias_kernel(const float* __restrict__ E,
                                                   const float* __restrict__ bp) {
    int idx = blockIdx.x * 256 + threadIdx.x;       // 65536
    int n = idx >> 6, o = idx & 63;
    float acc = 0.f;
#pragma unroll
    for (int d = 0; d < EMB; d++) acc += E[n * EMB + d] * bp[d * DOUT + o];
    g_bias[idx] = acc;
}

// ---------------------------------------------------------------------------
// K2: e[b,i,j] = exp(-sum_d |pa[b,i,d]-pa[b,j,d]|)
// 4 independent accumulators (break the serial FADD chain), float4 smem loads.
// grid (16 j-tiles of 64, 8 i-tiles of 128, 8 b)
// ---------------------------------------------------------------------------
__global__ __launch_bounds__(256) void e_kernel(const float* __restrict__ pa) {
    const int b = blockIdx.z;
    const int i0 = blockIdx.y * 128;
    const int j0 = blockIdx.x * 64;
    const int t = threadIdx.x;
    __shared__ float paI[128][20];
    __shared__ float paJ[64][20];
    const float* paB = pa + (size_t)b * NN * DPE;
#pragma unroll
    for (int l = 0; l < 2; l++) {
        int idx4 = t + l * 256;                 // 512 float4s
        int r = idx4 >> 2, q4 = (idx4 & 3) * 4;
        *reinterpret_cast<float4*>(&paI[r][q4]) =
            *reinterpret_cast<const float4*>(&paB[(i0 + r) * DPE + q4]);
    }
    if (t < 256) {
        int idx4 = t;                            // 256 float4s
        int r = idx4 >> 2, q4 = (idx4 & 3) * 4;
        *reinterpret_cast<float4*>(&paJ[r][q4]) =
            *reinterpret_cast<const float4*>(&paB[(j0 + r) * DPE + q4]);
    }
    __syncthreads();

    const int tj = t & 63, tig = t >> 6;
    float pj[16];
#pragma unroll
    for (int q = 0; q < 4; q++) {
        float4 v = *reinterpret_cast<const float4*>(&paJ[tj][q * 4]);
        pj[q * 4 + 0] = v.x; pj[q * 4 + 1] = v.y; pj[q * 4 + 2] = v.z; pj[q * 4 + 3] = v.w;
    }

    float* outBase = g_e + ((size_t)b * NN + i0) * NN + j0;
#pragma unroll 4
    for (int s = 0; s < 32; s++) {
        int i = tig * 32 + s;
        float4 p0 = *reinterpret_cast<const float4*>(&paI[i][0]);
        float4 p1 = *reinterpret_cast<const float4*>(&paI[i][4]);
        float4 p2 = *reinterpret_cast<const float4*>(&paI[i][8]);
        float4 p3 = *reinterpret_cast<const float4*>(&paI[i][12]);
        float a0 = fabsf(p0.x - pj[0])  + fabsf(p1.x - pj[4])
                 + fabsf(p2.x - pj[8])  + fabsf(p3.x - pj[12]);
        float a1 = fabsf(p0.y - pj[1])  + fabsf(p1.y - pj[5])
                 + fabsf(p2.y - pj[9])  + fabsf(p3.y - pj[13]);
        float a2 = fabsf(p0.z - pj[2])  + fabsf(p1.z - pj[6])
                 + fabsf(p2.z - pj[10]) + fabsf(p3.z - pj[14]);
        float a3 = fabsf(p0.w - pj[3])  + fabsf(p1.w - pj[7])
                 + fabsf(p2.w - pj[11]) + fabsf(p3.w - pj[15]);
        float acc = (a0 + a1) + (a2 + a3);
        outBase[(size_t)i * NN + tj] = __expf(-acc);
    }
}

// K3: Sinv[b,i] = 1 / sum_j e[b,i,j]   (row sum == column sum by symmetry)
__global__ __launch_bounds__(256) void rowsum_kernel() {
    int row = blockIdx.x * 8 + (threadIdx.x >> 5);   // 8192 rows
    int lane = threadIdx.x & 31;
    const float* r = g_e + (size_t)row * NN;
    float s = 0.f;
    for (int j = lane; j < NN; j += 32) s += r[j];
#pragma unroll
    for (int o = 16; o > 0; o >>= 1) s += __shfl_xor_sync(0xffffffffu, s, o);
    if (lane == 0) g_Sinv[row] = 1.0f / s;
}

// ---------------------------------------------------------------------------
// K4: sxT[m][b][d] = sum_c e[b,m,c] * (x[b,c,d] * Sinv[b,c])
// 64x64 tile, 128 threads, 8x4 per-thread register tile, K-step 32.
// grid (16 m-tiles, 8 b)
// ---------------------------------------------------------------------------
__global__ __launch_bounds__(128) void sx_kernel(const float* __restrict__ x) {
    const int b = blockIdx.y, m0 = blockIdx.x * 64;
    const int t = threadIdx.x;
    const int tm = t >> 4, td = t & 15;     // tm 0..7 (8 m-rows each), td 0..15 (4 d each)
    __shared__ float aS[64][36];            // [m][k], padded, 16B-aligned rows
    __shared__ float bS[32][64];            // [k][d]
    float acc[8][4] = {};
    const float* eB = g_e + ((size_t)b * NN + m0) * NN;
    const float* xB = x + (size_t)b * NN * DIN;
    const float* sI = g_Sinv + b * NN;

    for (int c0 = 0; c0 < NN; c0 += 32) {
        __syncthreads();
#pragma unroll
        for (int l = 0; l < 4; l++) {
            int idx = t + l * 128;          // 512 float4s: 64 rows x 8 quads
            int r = idx >> 3, c4 = (idx & 7) * 4;
            *reinterpret_cast<float4*>(&aS[r][c4]) =
                *reinterpret_cast<const float4*>(&eB[(size_t)r * NN + c0 + c4]);
        }
#pragma unroll
        for (int l = 0; l < 4; l++) {
            int idx = t + l * 128;          // 512 float4s: 32 rows x 16 quads
            int r = idx >> 4, d4 = (idx & 15) * 4;
            float4 v = *reinterpret_cast<const float4*>(&xB[(size_t)(c0 + r) * DIN + d4]);
            float s = sI[c0 + r];
            v.x *= s; v.y *= s; v.z *= s; v.w *= s;
            *reinterpret_cast<float4*>(&bS[r][d4]) = v;
        }
        __syncthreads();
#pragma unroll
        for (int kk = 0; kk < 32; kk++) {
            float4 bv = *reinterpret_cast<const float4*>(&bS[kk][td * 4]);
            float a[8];
#pragma unroll
            for (int r = 0; r < 8; r++) a[r] = aS[tm * 8 + r][kk];
#pragma unroll
            for (int r = 0; r < 8; r++) {
                acc[r][0] += a[r] * bv.x; acc[r][1] += a[r] * bv.y;
                acc[r][2] += a[r] * bv.z; acc[r][3] += a[r] * bv.w;
            }
        }
    }
#pragma unroll
    for (int r = 0; r < 8; r++) {
        int m = m0 + tm * 8 + r;
        float4 v = make_float4(acc[r][0], acc[r][1], acc[r][2], acc[r][3]);
        *reinterpret_cast<float4*>(&g_sxT[((size_t)m * BB + b) * DIN + td * 4]) = v;
    }
}

// ---------------------------------------------------------------------------
// K5: s1[n][bd] = sum_m sim[n,m] * sxT[m][bd]   (1024x512x1024 GEMM)
// same scheme as K4.  grid (16 n-tiles, 8 bd-tiles)
// ---------------------------------------------------------------------------
__global__ __launch_bounds__(128) void s1_kernel() {
    const int n0 = blockIdx.x * 64, bd0 = blockIdx.y * 64;
    const int t = threadIdx.x;
    const int tm = t >> 4, td = t & 15;
    __shared__ float aS[64][36];
    __shared__ float bS[32][64];
    float acc[8][4] = {};

    for (int c0 = 0; c0 < NN; c0 += 32) {
        __syncthreads();
#pragma unroll
        for (int l = 0; l < 4; l++) {
            int idx = t + l * 128;
            int r = idx >> 3, c4 = (idx & 7) * 4;
            *reinterpret_cast<float4*>(&aS[r][c4]) =
                *reinterpret_cast<const float4*>(&g_sim[(size_t)(n0 + r) * NN + c0 + c4]);
        }
#pragma unroll
        for (int l = 0; l < 4; l++) {
            int idx = t + l * 128;
            int r = idx >> 4, d4 = (idx & 15) * 4;
            *reinterpret_cast<float4*>(&bS[r][d4]) =
                *reinterpret_cast<const float4*>(&g_sxT[(size_t)(c0 + r) * (BB * DIN) + bd0 + d4]);
        }
        __syncthreads();
#pragma unroll
        for (int kk = 0; kk < 32; kk++) {
            float4 bv = *reinterpret_cast<const float4*>(&bS[kk][td * 4]);
            float a[8];
#pragma unroll
            for (int r = 0; r < 8; r++) a[r] = aS[tm * 8 + r][kk];
#pragma unroll
            for (int r = 0; r < 8; r++) {
                acc[r][0] += a[r] * bv.x; acc[r][1] += a[r] * bv.y;
                acc[r][2] += a[r] * bv.z; acc[r][3] += a[r] * bv.w;
            }
        }
    }
#pragma unroll
    for (int r = 0; r < 8; r++) {
        int n = n0 + tm * 8 + r;
        float4 v = make_float4(acc[r][0], acc[r][1], acc[r][2], acc[r][3]);
        *reinterpret_cast<float4*>(&g_s1[(size_t)n * (BB * DIN) + bd0 + td * 4]) = v;
    }
}

// ---------------------------------------------------------------------------
// K6: out[b,n,o] = bias[n,o] + sum_i sx[n,b,i] w[n,0,i,o] + sum_i s1[n,b,i] w[n,1,i,o]
// one block per n; vectorized w loads (LDS.128 over o), broadcast xg loads;
// i-range split across two thread halves with a smem reduce.
// ---------------------------------------------------------------------------
__global__ __launch_bounds__(256) void out_kernel(float* __restrict__ out) {
    const int n = blockIdx.x, t = threadIdx.x;
    __shared__ float wS[KIO];            // 32 KB, layout [k][i][o]
    __shared__ float xgS[2][BB][DIN];    // 4 KB
    __shared__ float bS[DOUT];
    __shared__ float red[128][4];        // 2 KB
    const float* wp = g_w + (size_t)n * KIO;
#pragma unroll
    for (int l = 0; l < 8; l++) {
        int idx4 = t + l * 256;          // 2048 float4s
        *reinterpret_cast<float4*>(&wS[idx4 * 4]) =
            *reinterpret_cast<const float4*>(&wp[idx4 * 4]);
    }
    {
        // 256 float4s: first 128 from sxT row, next 128 from s1 row
        float* xgFlat = &xgS[0][0][0];
        const float* src = (t < 128) ? (g_sxT + (size_t)n * (BB * DIN) + t * 4)
                                     : (g_s1  + (size_t)n * (BB * DIN) + (t - 128) * 4);
        *reinterpret_cast<float4*>(&xgFlat[t * 4]) =
            *reinterpret_cast<const float4*>(src);
    }
    if (t < DOUT) bS[t] = g_bias[n * DOUT + t];
    __syncthreads();

    const int half = t >> 7;             // 0 or 1 (i-range split)
    const int q = t & 127;               // output quad id
    const int b = q >> 4, o4 = (q & 15) * 4;
    float4 acc = make_float4(0.f, 0.f, 0.f, 0.f);
    const int i0 = half * 32;
#pragma unroll 8
    for (int ii = 0; ii < 32; ii++) {
        int i = i0 + ii;
        float4 w0 = *reinterpret_cast<const float4*>(&wS[i * 64 + o4]);
        float4 w1 = *reinterpret_cast<const float4*>(&wS[4096 + i * 64 + o4]);
        float x0 = xgS[0][b][i];
        float x1 = xgS[1][b][i];
        acc.x += x0 * w0.x + x1 * w1.x;
        acc.y += x0 * w0.y + x1 * w1.y;
        acc.z += x0 * w0.z + x1 * w1.z;
        acc.w += x0 * w0.w + x1 * w1.w;
    }
    if (half == 1) *reinterpret_cast<float4*>(&red[q][0]) = acc;
    __syncthreads();
    if (half == 0) {
        float4 r = *reinterpret_cast<const float4*>(&red[q][0]);
        float4 v;
        v.x = acc.x + r.x + bS[o4 + 0];
        v.y = acc.y + r.y + bS[o4 + 1];
        v.z = acc.z + r.z + bS[o4 + 2];
        v.w = acc.w + r.w + bS[o4 + 3];
        *reinterpret_cast<float4*>(&out[((size_t)b * NN + n) * DOUT + o4]) = v;
    }
}

// ---------------------------------------------------------------------------
extern "C" void kernel_launch(void* const* d_in, const int* in_sizes, int n_in,
                              void* d_out, int out_size) {
    const float* x    = (const float*)d_in[0];   // [8,1024,64]
    const float* E    = (const float*)d_in[1];   // [1024,16]
    const float* pa   = (const float*)d_in[2];   // [8,1024,16]
    const float* Wp   = (const float*)d_in[3];   // [16,2,64,64]
    const float* bp   = (const float*)d_in[4];   // [16,64]
    float* out = (float*)d_out;                  // [8,1024,64]

    sim_kernel<<<NN, 256>>>(E);
    weights_kernel<<<dim3(KIO / 256, NN / 128), 256>>>(E, Wp);
    bias_kernel<<<NN * DOUT / 256, 256>>>(E, bp);
    e_kernel<<<dim3(NN / 64, NN / 128, BB), 256>>>(pa);
    rowsum_kernel<<<BB * NN / 8, 256>>>();
    sx_kernel<<<dim3(NN / 64, BB), 128>>>(x);
    s1_kernel<<<dim3(NN / 64, BB * DIN / 64), 128>>>();
    out_kernel<<<NN, 256>>>(out);
}

// round 8
// speedup vs baseline: 1.5913x; 1.3610x over previous
#include <cuda_runtime.h>
#include <cuda_bf16.h>
#include <cstdint>

#define NN 1024
#define BB 8
#define DIN 64
#define DOUT 64
#define EMB 16
#define DPE 16
#define KIO 8192   // 2*64*64

// ---- device scratch (no allocations allowed) ----
__device__ __nv_bfloat16 g_e_hi[(size_t)BB * NN * NN];   // 16 MB
__device__ __nv_bfloat16 g_e_lo[(size_t)BB * NN * NN];   // 16 MB
__device__ __nv_bfloat16 g_sim_hi[NN * NN];              // 2 MB
__device__ __nv_bfloat16 g_sim_lo[NN * NN];              // 2 MB
__device__ __nv_bfloat16 g_xs_hi[BB * NN * DIN];         // 1 MB  (x*Sinv)
__device__ __nv_bfloat16 g_xs_lo[BB * NN * DIN];         // 1 MB
__device__ __nv_bfloat16 g_sxT_hi[NN * BB * DIN];        // 1 MB
__device__ __nv_bfloat16 g_sxT_lo[NN * BB * DIN];        // 1 MB
__device__ float g_w[NN * KIO];           // 32 MB  weights[n][k][i][o]
__device__ float g_bias[NN * DOUT];       // 256 KB
__device__ float g_Sinv[BB * NN];         // 32 KB
__device__ float g_sxT[NN * BB * DIN];    // 2 MB   sx as [m][b][d]
__device__ float g_s1[NN * BB * DIN];     // 2 MB   sim@sx as [n][b][d]

// ---------- helpers ----------
static __device__ __forceinline__ unsigned int s2u(const void* p) {
    return (unsigned int)__cvta_generic_to_shared(p);
}
static __device__ __forceinline__ void ldsm_x4(unsigned r[4], unsigned int addr) {
    asm volatile("ldmatrix.sync.aligned.m8n8.x4.shared.b16 {%0,%1,%2,%3}, [%4];"
        : "=r"(r[0]), "=r"(r[1]), "=r"(r[2]), "=r"(r[3]) : "r"(addr));
}
static __device__ __forceinline__ void ldsm_x4_t(unsigned r[4], unsigned int addr) {
    asm volatile("ldmatrix.sync.aligned.m8n8.x4.trans.shared.b16 {%0,%1,%2,%3}, [%4];"
        : "=r"(r[0]), "=r"(r[1]), "=r"(r[2]), "=r"(r[3]) : "r"(addr));
}
static __device__ __forceinline__ void mma16816(float c[4], const unsigned a[4], const unsigned b0, const unsigned b1) {
    asm volatile("mma.sync.aligned.m16n8k16.row.col.f32.bf16.bf16.f32 "
        "{%0,%1,%2,%3}, {%4,%5,%6,%7}, {%8,%9}, {%0,%1,%2,%3};"
        : "+f"(c[0]), "+f"(c[1]), "+f"(c[2]), "+f"(c[3])
        : "r"(a[0]), "r"(a[1]), "r"(a[2]), "r"(a[3]), "r"(b0), "r"(b1));
}
static __device__ __forceinline__ void split_store(float v, __nv_bfloat16* hi, __nv_bfloat16* lo, size_t off) {
    __nv_bfloat16 h = __float2bfloat16(v);
    hi[off] = h;
    lo[off] = __float2bfloat16(v - __bfloat162float(h));
}

// ---------------------------------------------------------------------------
// K0: sim = softmax(relu(E E^T), axis=1) -> bf16 hi/lo.  one block per row
// ---------------------------------------------------------------------------
__global__ __launch_bounds__(256) void sim_kernel(const float* __restrict__ E) {
    const int i = blockIdx.x;
    const int t = threadIdx.x;
    __shared__ float Ei[EMB];
    __shared__ float red[256];
    if (t < EMB) Ei[t] = E[i * EMB + t];
    __syncthreads();

    float v[4];
    float mx = -1e30f;
#pragma unroll
    for (int r = 0; r < 4; r++) {
        int j = t + r * 256;
        const float4* Ej = reinterpret_cast<const float4*>(E + j * EMB);
        float acc = 0.f;
#pragma unroll
        for (int q = 0; q < 4; q++) {
            float4 e4 = Ej[q];
            acc += Ei[q * 4 + 0] * e4.x + Ei[q * 4 + 1] * e4.y
                 + Ei[q * 4 + 2] * e4.z + Ei[q * 4 + 3] * e4.w;
        }
        acc = fmaxf(acc, 0.f);
        v[r] = acc;
        mx = fmaxf(mx, acc);
    }
    red[t] = mx; __syncthreads();
    for (int s = 128; s > 0; s >>= 1) { if (t < s) red[t] = fmaxf(red[t], red[t + s]); __syncthreads(); }
    mx = red[0]; __syncthreads();

    float sum = 0.f;
#pragma unroll
    for (int r = 0; r < 4; r++) { v[r] = __expf(v[r] - mx); sum += v[r]; }
    red[t] = sum; __syncthreads();
    for (int s = 128; s > 0; s >>= 1) { if (t < s) red[t] += red[t + s]; __syncthreads(); }
    float inv = 1.0f / red[0];
#pragma unroll
    for (int r = 0; r < 4; r++)
        split_store(v[r] * inv, g_sim_hi, g_sim_lo, (size_t)i * NN + t + r * 256);
}

// ---------------------------------------------------------------------------
// K1: weights[n, kio] = sum_d E[n,d] * Wp[d, kio]
// ---------------------------------------------------------------------------
__global__ __launch_bounds__(256) void weights_kernel(const float* __restrict__ E,
                                                      const float* __restrict__ Wp) {
    const int t = threadIdx.x;
    const int kio = blockIdx.x * 256 + t;
    const int n0 = blockIdx.y * 128;

    float w[EMB];
#pragma unroll
    for (int d = 0; d < EMB; d++) w[d] = Wp[d * KIO + kio];   // coalesced

    __shared__ float Es[128][20];
#pragma unroll
    for (int l = 0; l < 2; l++) {
        int idx4 = t + l * 256;
        int r = idx4 >> 2, q4 = (idx4 & 3) * 4;
        *reinterpret_cast<float4*>(&Es[r][q4]) =
            *reinterpret_cast<const float4*>(&E[(n0 + r) * EMB + q4]);
    }
    __syncthreads();

    float* outp = g_w + (size_t)n0 * KIO + kio;
#pragma unroll 4
    for (int nn = 0; nn < 128; nn++) {
        float4 e0 = *reinterpret_cast<const float4*>(&Es[nn][0]);
        float4 e1 = *reinterpret_cast<const float4*>(&Es[nn][4]);
        float4 e2 = *reinterpret_cast<const float4*>(&Es[nn][8]);
        float4 e3 = *reinterpret_cast<const float4*>(&Es[nn][12]);
        float a0 = e0.x * w[0] + e0.y * w[1] + e0.z * w[2] + e0.w * w[3]
                 + e1.x * w[4] + e1.y * w[5] + e1.z * w[6] + e1.w * w[7];
        float a1 = e2.x * w[8] + e2.y * w[9] + e2.z * w[10] + e2.w * w[11]
                 + e3.x * w[12] + e3.y * w[13] + e3.z * w[14] + e3.w * w[15];
        outp[(size_t)nn * KIO] = a0 + a1;
    }
}

// K1b: bias[n,o] = sum_d E[n,d] * bp[d,o]
__global__ __launch_bounds__(256) void bias_kernel(const float* __restrict__ E,
                                                   const float* __restrict__ bp) {
    int idx = blockIdx.x * 256 + threadIdx.x;       // 65536
    int n = idx >> 6, o = idx & 63;
    float acc = 0.f;
#pragma unroll
    for (int d = 0; d < EMB; d++) acc += E[n * EMB + d] * bp[d * DOUT + o];
    g_bias[idx] = acc;
}

// ---------------------------------------------------------------------------
// K2: e[b,i,j] = exp(-sum_d |pa[b,i,d]-pa[b,j,d]|)  ->  bf16 hi/lo
// ---------------------------------------------------------------------------
__global__ __launch_bounds__(256) void e_kernel(const float* __restrict__ pa) {
    const int b = blockIdx.z;
    const int i0 = blockIdx.y * 128;
    const int j0 = blockIdx.x * 64;
    const int t = threadIdx.x;
    __shared__ float paI[128][20];
    __shared__ float paJ[64][20];
    const float* paB = pa + (size_t)b * NN * DPE;
#pragma unroll
    for (int l = 0; l < 2; l++) {
        int idx4 = t + l * 256;
        int r = idx4 >> 2, q4 = (idx4 & 3) * 4;
        *reinterpret_cast<float4*>(&paI[r][q4]) =
            *reinterpret_cast<const float4*>(&paB[(i0 + r) * DPE + q4]);
    }
    if (t < 256) {
        int r = t >> 2, q4 = (t & 3) * 4;
        *reinterpret_cast<float4*>(&paJ[r][q4]) =
            *reinterpret_cast<const float4*>(&paB[(j0 + r) * DPE + q4]);
    }
    __syncthreads();

    const int tj = t & 63, tig = t >> 6;
    float pj[16];
#pragma unroll
    for (int q = 0; q < 4; q++) {
        float4 v = *reinterpret_cast<const float4*>(&paJ[tj][q * 4]);
        pj[q * 4 + 0] = v.x; pj[q * 4 + 1] = v.y; pj[q * 4 + 2] = v.z; pj[q * 4 + 3] = v.w;
    }

    __nv_bfloat16* outHi = g_e_hi + ((size_t)b * NN + i0) * NN + j0;
    __nv_bfloat16* outLo = g_e_lo + ((size_t)b * NN + i0) * NN + j0;
#pragma unroll 4
    for (int s = 0; s < 32; s++) {
        int i = tig * 32 + s;
        float4 p0 = *reinterpret_cast<const float4*>(&paI[i][0]);
        float4 p1 = *reinterpret_cast<const float4*>(&paI[i][4]);
        float4 p2 = *reinterpret_cast<const float4*>(&paI[i][8]);
        float4 p3 = *reinterpret_cast<const float4*>(&paI[i][12]);
        float a0 = fabsf(p0.x - pj[0])  + fabsf(p1.x - pj[4])
                 + fabsf(p2.x - pj[8])  + fabsf(p3.x - pj[12]);
        float a1 = fabsf(p0.y - pj[1])  + fabsf(p1.y - pj[5])
                 + fabsf(p2.y - pj[9])  + fabsf(p3.y - pj[13]);
        float a2 = fabsf(p0.z - pj[2])  + fabsf(p1.z - pj[6])
                 + fabsf(p2.z - pj[10]) + fabsf(p3.z - pj[14]);
        float a3 = fabsf(p0.w - pj[3])  + fabsf(p1.w - pj[7])
                 + fabsf(p2.w - pj[11]) + fabsf(p3.w - pj[15]);
        float v = __expf(-((a0 + a1) + (a2 + a3)));
        __nv_bfloat16 h = __float2bfloat16(v);
        outHi[(size_t)i * NN + tj] = h;
        outLo[(size_t)i * NN + tj] = __float2bfloat16(v - __bfloat162float(h));
    }
}

// K3: Sinv[b,i] = 1 / sum_j e[b,i,j]   (row sum == column sum by symmetry)
__global__ __launch_bounds__(256) void rowsum_kernel() {
    int row = blockIdx.x * 8 + (threadIdx.x >> 5);   // 8192 rows
    int lane = threadIdx.x & 31;
    const __nv_bfloat162* rh = reinterpret_cast<const __nv_bfloat162*>(g_e_hi + (size_t)row * NN);
    const __nv_bfloat162* rl = reinterpret_cast<const __nv_bfloat162*>(g_e_lo + (size_t)row * NN);
    float s = 0.f;
    for (int j = lane; j < NN / 2; j += 32) {
        float2 h = __bfloat1622float2(rh[j]);
        float2 l = __bfloat1622float2(rl[j]);
        s += (h.x + l.x) + (h.y + l.y);
    }
#pragma unroll
    for (int o = 16; o > 0; o >>= 1) s += __shfl_xor_sync(0xffffffffu, s, o);
    if (lane == 0) g_Sinv[row] = 1.0f / s;
}

// K3b: xs[b,c,d] = x[b,c,d] * Sinv[b,c]  ->  bf16 hi/lo
__global__ __launch_bounds__(256) void xs_kernel(const float* __restrict__ x) {
    int idx4 = blockIdx.x * 256 + threadIdx.x;       // 131072 float4s
    float4 v = *reinterpret_cast<const float4*>(&x[(size_t)idx4 * 4]);
    int b = idx4 >> 14;
    int c = (idx4 >> 4) & 1023;
    float s = g_Sinv[b * NN + c];
    v.x *= s; v.y *= s; v.z *= s; v.w *= s;
    __nv_bfloat162 h0 = __floats2bfloat162_rn(v.x, v.y);
    __nv_bfloat162 h1 = __floats2bfloat162_rn(v.z, v.w);
    float2 hf0 = __bfloat1622float2(h0);
    float2 hf1 = __bfloat1622float2(h1);
    __nv_bfloat162 l0 = __floats2bfloat162_rn(v.x - hf0.x, v.y - hf0.y);
    __nv_bfloat162 l1 = __floats2bfloat162_rn(v.z - hf1.x, v.w - hf1.y);
    *reinterpret_cast<__nv_bfloat162*>(&g_xs_hi[(size_t)idx4 * 4]) = h0;
    *reinterpret_cast<__nv_bfloat162*>(&g_xs_hi[(size_t)idx4 * 4 + 2]) = h1;
    *reinterpret_cast<__nv_bfloat162*>(&g_xs_lo[(size_t)idx4 * 4]) = l0;
    *reinterpret_cast<__nv_bfloat162*>(&g_xs_lo[(size_t)idx4 * 4 + 2]) = l1;
}

// ---------------------------------------------------------------------------
// K4: sxT[m][b][d] = sum_c e[b,m,c] * xs[b,c,d]   via bf16 mma (3-pass split)
// BM=64, BN=64, BK=32, 4 warps stacked on M (16 rows each).
// grid (16 m-tiles, 8 b)
// ---------------------------------------------------------------------------
__global__ __launch_bounds__(128) void sx_mma_kernel() {
    const int b = blockIdx.y, m0 = blockIdx.x * 64;
    const int t = threadIdx.x;
    const int warp = t >> 5, lane = t & 31;
    const int g = lane >> 2, tg = lane & 3;

    __shared__ __nv_bfloat16 Ah[64][40], Al[64][40];
    __shared__ __nv_bfloat16 Bh[32][72], Bl[32][72];

    const __nv_bfloat16* eHi = g_e_hi + ((size_t)b * NN + m0) * NN;
    const __nv_bfloat16* eLo = g_e_lo + ((size_t)b * NN + m0) * NN;
    const __nv_bfloat16* xHi = g_xs_hi + (size_t)b * NN * DIN;
    const __nv_bfloat16* xLo = g_xs_lo + (size_t)b * NN * DIN;

    float acc[8][4] = {};

    // ldmatrix lane address components
    const int lrow = lane & 15;               // (mat&1)*8 + r
    const int lcol = (lane & 16) >> 1;        // (mat>>1)*8

    for (int c0 = 0; c0 < NN; c0 += 32) {
        __syncthreads();
#pragma unroll
        for (int l = 0; l < 2; l++) {
            int idx = t + l * 128;
            int r = idx >> 2, q = (idx & 3) * 8;     // A: 64 rows x 4 quads
            *reinterpret_cast<uint4*>(&Ah[r][q]) =
                *reinterpret_cast<const uint4*>(&eHi[(size_t)r * NN + c0 + q]);
            *reinterpret_cast<uint4*>(&Al[r][q]) =
                *reinterpret_cast<const uint4*>(&eLo[(size_t)r * NN + c0 + q]);
        }
#pragma unroll
        for (int l = 0; l < 2; l++) {
            int idx = t + l * 128;
            int r = idx >> 3, q = (idx & 7) * 8;     // B: 32 rows x 8 quads
            *reinterpret_cast<uint4*>(&Bh[r][q]) =
                *reinterpret_cast<const uint4*>(&xHi[(size_t)(c0 + r) * DIN + q]);
            *reinterpret_cast<uint4*>(&Bl[r][q]) =
                *reinterpret_cast<const uint4*>(&xLo[(size_t)(c0 + r) * DIN + q]);
        }
        __syncthreads();

#pragma unroll
        for (int k16 = 0; k16 < 2; k16++) {
            unsigned A_h[4], A_l[4];
            ldsm_x4(A_h, s2u(&Ah[warp * 16 + lrow][k16 * 16 + lcol]));
            ldsm_x4(A_l, s2u(&Al[warp * 16 + lrow][k16 * 16 + lcol]));
            unsigned Bfh[8][2], Bfl[8][2];
#pragma unroll
            for (int nb = 0; nb < 4; nb++) {
                unsigned tmp[4];
                ldsm_x4_t(tmp, s2u(&Bh[k16 * 16 + lrow][nb * 16 + lcol]));
                Bfh[nb * 2][0] = tmp[0]; Bfh[nb * 2][1] = tmp[1];
                Bfh[nb * 2 + 1][0] = tmp[2]; Bfh[nb * 2 + 1][1] = tmp[3];
                ldsm_x4_t(tmp, s2u(&Bl[k16 * 16 + lrow][nb * 16 + lcol]));
                Bfl[nb * 2][0] = tmp[0]; Bfl[nb * 2][1] = tmp[1];
                Bfl[nb * 2 + 1][0] = tmp[2]; Bfl[nb * 2 + 1][1] = tmp[3];
            }
#pragma unroll
            for (int f = 0; f < 8; f++) {
                mma16816(acc[f], A_h, Bfh[f][0], Bfh[f][1]);
                mma16816(acc[f], A_h, Bfl[f][0], Bfl[f][1]);
                mma16816(acc[f], A_l, Bfh[f][0], Bfh[f][1]);
            }
        }
    }

    // epilogue: fp32 + bf16 hi/lo split for s1's B operand
    const int m_lo = m0 + warp * 16 + g;
#pragma unroll
    for (int f = 0; f < 8; f++) {
        int col = f * 8 + tg * 2;
#pragma unroll
        for (int h = 0; h < 2; h++) {
            int m = m_lo + h * 8;
            float vx = acc[f][h * 2], vy = acc[f][h * 2 + 1];
            size_t o = ((size_t)m * BB + b) * DIN + col;
            *reinterpret_cast<float2*>(&g_sxT[o]) = make_float2(vx, vy);
            __nv_bfloat162 hv = __floats2bfloat162_rn(vx, vy);
            float2 hf = __bfloat1622float2(hv);
            __nv_bfloat162 lv = __floats2bfloat162_rn(vx - hf.x, vy - hf.y);
            *reinterpret_cast<__nv_bfloat162*>(&g_sxT_hi[o]) = hv;
            *reinterpret_cast<__nv_bfloat162*>(&g_sxT_lo[o]) = lv;
        }
    }
}

// ---------------------------------------------------------------------------
// K5: s1[n][bd] = sum_m sim[n,m] * sxT[m][bd]   via bf16 mma (3-pass split)
// grid (16 n-tiles, 8 bd-tiles)
// ---------------------------------------------------------------------------
__global__ __launch_bounds__(128) void s1_mma_kernel() {
    const int n0 = blockIdx.x * 64, bd0 = blockIdx.y * 64;
    const int t = threadIdx.x;
    const int warp = t >> 5, lane = t & 31;
    const int g = lane >> 2, tg = lane & 3;

    __shared__ __nv_bfloat16 Ah[64][40], Al[64][40];
    __shared__ __nv_bfloat16 Bh[32][72], Bl[32][72];

    const __nv_bfloat16* aHi = g_sim_hi + (size_t)n0 * NN;
    const __nv_bfloat16* aLo = g_sim_lo + (size_t)n0 * NN;

    float acc[8][4] = {};
    const int lrow = lane & 15;
    const int lcol = (lane & 16) >> 1;

    for (int c0 = 0; c0 < NN; c0 += 32) {
        __syncthreads();
#pragma unroll
        for (int l = 0; l < 2; l++) {
            int idx = t + l * 128;
            int r = idx >> 2, q = (idx & 3) * 8;
            *reinterpret_cast<uint4*>(&Ah[r][q]) =
                *reinterpret_cast<const uint4*>(&aHi[(size_t)r * NN + c0 + q]);
            *reinterpret_cast<uint4*>(&Al[r][q]) =
                *reinterpret_cast<const uint4*>(&aLo[(size_t)r * NN + c0 + q]);
        }
#pragma unroll
        for (int l = 0; l < 2; l++) {
            int idx = t + l * 128;
            int r = idx >> 3, q = (idx & 7) * 8;
            *reinterpret_cast<uint4*>(&Bh[r][q]) =
                *reinterpret_cast<const uint4*>(&g_sxT_hi[(size_t)(c0 + r) * (BB * DIN) + bd0 + q]);
            *reinterpret_cast<uint4*>(&Bl[r][q]) =
                *reinterpret_cast<const uint4*>(&g_sxT_lo[(size_t)(c0 + r) * (BB * DIN) + bd0 + q]);
        }
        __syncthreads();

#pragma unroll
        for (int k16 = 0; k16 < 2; k16++) {
            unsigned A_h[4], A_l[4];
            ldsm_x4(A_h, s2u(&Ah[warp * 16 + lrow][k16 * 16 + lcol]));
            ldsm_x4(A_l, s2u(&Al[warp * 16 + lrow][k16 * 16 + lcol]));
            unsigned Bfh[8][2], Bfl[8][2];
#pragma unroll
            for (int nb = 0; nb < 4; nb++) {
                unsigned tmp[4];
                ldsm_x4_t(tmp, s2u(&Bh[k16 * 16 + lrow][nb * 16 + lcol]));
                Bfh[nb * 2][0] = tmp[0]; Bfh[nb * 2][1] = tmp[1];
                Bfh[nb * 2 + 1][0] = tmp[2]; Bfh[nb * 2 + 1][1] = tmp[3];
                ldsm_x4_t(tmp, s2u(&Bl[k16 * 16 + lrow][nb * 16 + lcol]));
                Bfl[nb * 2][0] = tmp[0]; Bfl[nb * 2][1] = tmp[1];
                Bfl[nb * 2 + 1][0] = tmp[2]; Bfl[nb * 2 + 1][1] = tmp[3];
            }
#pragma unroll
            for (int f = 0; f < 8; f++) {
                mma16816(acc[f], A_h, Bfh[f][0], Bfh[f][1]);
                mma16816(acc[f], A_h, Bfl[f][0], Bfl[f][1]);
                mma16816(acc[f], A_l, Bfh[f][0], Bfh[f][1]);
            }
        }
    }

    const int n_lo = n0 + warp * 16 + g;
#pragma unroll
    for (int f = 0; f < 8; f++) {
        int col = bd0 + f * 8 + tg * 2;
#pragma unroll
        for (int h = 0; h < 2; h++) {
            int n = n_lo + h * 8;
            *reinterpret_cast<float2*>(&g_s1[(size_t)n * (BB * DIN) + col]) =
                make_float2(acc[f][h * 2], acc[f][h * 2 + 1]);
        }
    }
}

// ---------------------------------------------------------------------------
// K6: out[b,n,o] = bias[n,o] + sum_i sx[n,b,i] w[n,0,i,o] + sum_i s1[n,b,i] w[n,1,i,o]
// ---------------------------------------------------------------------------
__global__ __launch_bounds__(256) void out_kernel(float* __restrict__ out) {
    const int n = blockIdx.x, t = threadIdx.x;
    __shared__ float wS[KIO];            // 32 KB
    __shared__ float xgS[2][BB][DIN];    // 4 KB
    __shared__ float bS[DOUT];
    __shared__ float red[128][4];        // 2 KB
    const float* wp = g_w + (size_t)n * KIO;
#pragma unroll
    for (int l = 0; l < 8; l++) {
        int idx4 = t + l * 256;
        *reinterpret_cast<float4*>(&wS[idx4 * 4]) =
            *reinterpret_cast<const float4*>(&wp[idx4 * 4]);
    }
    {
        float* xgFlat = &xgS[0][0][0];
        const float* src = (t < 128) ? (g_sxT + (size_t)n * (BB * DIN) + t * 4)
                                     : (g_s1  + (size_t)n * (BB * DIN) + (t - 128) * 4);
        *reinterpret_cast<float4*>(&xgFlat[t * 4]) =
            *reinterpret_cast<const float4*>(src);
    }
    if (t < DOUT) bS[t] = g_bias[n * DOUT + t];
    __syncthreads();

    const int half = t >> 7;
    const int q = t & 127;
    const int b = q >> 4, o4 = (q & 15) * 4;
    float4 acc = make_float4(0.f, 0.f, 0.f, 0.f);
    const int i0 = half * 32;
#pragma unroll 8
    for (int ii = 0; ii < 32; ii++) {
        int i = i0 + ii;
        float4 w0 = *reinterpret_cast<const float4*>(&wS[i * 64 + o4]);
        float4 w1 = *reinterpret_cast<const float4*>(&wS[4096 + i * 64 + o4]);
        float x0 = xgS[0][b][i];
        float x1 = xgS[1][b][i];
        acc.x += x0 * w0.x + x1 * w1.x;
        acc.y += x0 * w0.y + x1 * w1.y;
        acc.z += x0 * w0.z + x1 * w1.z;
        acc.w += x0 * w0.w + x1 * w1.w;
    }
    if (half == 1) *reinterpret_cast<float4*>(&red[q][0]) = acc;
    __syncthreads();
    if (half == 0) {
        float4 r = *reinterpret_cast<const float4*>(&red[q][0]);
        float4 v;
        v.x = acc.x + r.x + bS[o4 + 0];
        v.y = acc.y + r.y + bS[o4 + 1];
        v.z = acc.z + r.z + bS[o4 + 2];
        v.w = acc.w + r.w + bS[o4 + 3];
        *reinterpret_cast<float4*>(&out[((size_t)b * NN + n) * DOUT + o4]) = v;
    }
}

// ---------------------------------------------------------------------------
extern "C" void kernel_launch(void* const* d_in, const int* in_sizes, int n_in,
                              void* d_out, int out_size) {
    const float* x    = (const float*)d_in[0];   // [8,1024,64]
    const float* E    = (const float*)d_in[1];   // [1024,16]
    const float* pa   = (const float*)d_in[2];   // [8,1024,16]
    const float* Wp   = (const float*)d_in[3];   // [16,2,64,64]
    const float* bp   = (const float*)d_in[4];   // [16,64]
    float* out = (float*)d_out;                  // [8,1024,64]

    sim_kernel<<<NN, 256>>>(E);
    weights_kernel<<<dim3(KIO / 256, NN / 128), 256>>>(E, Wp);
    bias_kernel<<<NN * DOUT / 256, 256>>>(E, bp);
    e_kernel<<<dim3(NN / 64, NN / 128, BB), 256>>>(pa);
    rowsum_kernel<<<BB * NN / 8, 256>>>();
    xs_kernel<<<BB * NN * DIN / 1024, 256>>>(x);
    sx_mma_kernel<<<dim3(NN / 64, BB), 128>>>();
    s1_mma_kernel<<<dim3(NN / 64, BB * DIN / 64), 128>>>();
    out_kernel<<<NN, 256>>>(out);
}

// round 9
// speedup vs baseline: 2.1891x; 1.3757x over previous
#include <cuda_runtime.h>
#include <cuda_bf16.h>
#include <cstdint>

#define NN 1024
#define BB 8
#define DIN 64
#define DOUT 64
#define EMB 16
#define DPE 16
#define KIO 8192   // 2*64*64

// ---- device scratch (no allocations allowed) ----
__device__ __nv_bfloat16 g_e_hi[(size_t)BB * NN * NN];   // 16 MB
__device__ __nv_bfloat16 g_e_lo[(size_t)BB * NN * NN];   // 16 MB
__device__ __nv_bfloat16 g_sim_hi[NN * NN];              // 2 MB
__device__ __nv_bfloat16 g_sim_lo[NN * NN];              // 2 MB
__device__ __nv_bfloat16 g_xs_hi[BB * NN * DIN];         // 1 MB  (x*Sinv)
__device__ __nv_bfloat16 g_xs_lo[BB * NN * DIN];         // 1 MB
__device__ __nv_bfloat16 g_sxT_hi[NN * BB * DIN];        // 1 MB
__device__ __nv_bfloat16 g_sxT_lo[NN * BB * DIN];        // 1 MB
__device__ float g_w[NN * KIO];           // 32 MB  weights[n][k][i][o]
__device__ float g_bias[NN * DOUT];       // 256 KB
__device__ float g_part[BB * NN * 16];    // 512 KB row-sum partials (one slot per tile)
__device__ float g_Sinv[BB * NN];         // 32 KB
__device__ float g_sxT[NN * BB * DIN];    // 2 MB   sx as [m][b][d]
__device__ float g_s1[NN * BB * DIN];     // 2 MB   sim@sx as [n][b][d]

// ---------- helpers ----------
static __device__ __forceinline__ unsigned int s2u(const void* p) {
    return (unsigned int)__cvta_generic_to_shared(p);
}
static __device__ __forceinline__ void ldsm_x4(unsigned r[4], unsigned int addr) {
    asm volatile("ldmatrix.sync.aligned.m8n8.x4.shared.b16 {%0,%1,%2,%3}, [%4];"
        : "=r"(r[0]), "=r"(r[1]), "=r"(r[2]), "=r"(r[3]) : "r"(addr));
}
static __device__ __forceinline__ void ldsm_x4_t(unsigned r[4], unsigned int addr) {
    asm volatile("ldmatrix.sync.aligned.m8n8.x4.trans.shared.b16 {%0,%1,%2,%3}, [%4];"
        : "=r"(r[0]), "=r"(r[1]), "=r"(r[2]), "=r"(r[3]) : "r"(addr));
}
static __device__ __forceinline__ void mma16816(float c[4], const unsigned a[4], const unsigned b0, const unsigned b1) {
    asm volatile("mma.sync.aligned.m16n8k16.row.col.f32.bf16.bf16.f32 "
        "{%0,%1,%2,%3}, {%4,%5,%6,%7}, {%8,%9}, {%0,%1,%2,%3};"
        : "+f"(c[0]), "+f"(c[1]), "+f"(c[2]), "+f"(c[3])
        : "r"(a[0]), "r"(a[1]), "r"(a[2]), "r"(a[3]), "r"(b0), "r"(b1));
}
static __device__ __forceinline__ void cpa16(void* dst, const void* src) {
    unsigned int d = s2u(dst);
    asm volatile("cp.async.ca.shared.global [%0], [%1], 16;" :: "r"(d), "l"(src));
}
#define CP_COMMIT() asm volatile("cp.async.commit_group;" ::: "memory")
#define CP_WAIT1()  asm volatile("cp.async.wait_group 1;" ::: "memory")
#define CP_WAIT0()  asm volatile("cp.async.wait_group 0;" ::: "memory")

static __device__ __forceinline__ void split_store(float v, __nv_bfloat16* hi, __nv_bfloat16* lo, size_t off) {
    __nv_bfloat16 h = __float2bfloat16(v);
    hi[off] = h;
    lo[off] = __float2bfloat16(v - __bfloat162float(h));
}

// ---------------------------------------------------------------------------
// K0: sim = softmax(relu(E E^T), axis=1) -> bf16 hi/lo.  one block per row
// ---------------------------------------------------------------------------
__global__ __launch_bounds__(256) void sim_kernel(const float* __restrict__ E) {
    const int i = blockIdx.x;
    const int t = threadIdx.x;
    __shared__ float Ei[EMB];
    __shared__ float red[256];
    if (t < EMB) Ei[t] = E[i * EMB + t];
    __syncthreads();

    float v[4];
    float mx = -1e30f;
#pragma unroll
    for (int r = 0; r < 4; r++) {
        int j = t + r * 256;
        const float4* Ej = reinterpret_cast<const float4*>(E + j * EMB);
        float acc = 0.f;
#pragma unroll
        for (int q = 0; q < 4; q++) {
            float4 e4 = Ej[q];
            acc += Ei[q * 4 + 0] * e4.x + Ei[q * 4 + 1] * e4.y
                 + Ei[q * 4 + 2] * e4.z + Ei[q * 4 + 3] * e4.w;
        }
        acc = fmaxf(acc, 0.f);
        v[r] = acc;
        mx = fmaxf(mx, acc);
    }
    red[t] = mx; __syncthreads();
    for (int s = 128; s > 0; s >>= 1) { if (t < s) red[t] = fmaxf(red[t], red[t + s]); __syncthreads(); }
    mx = red[0]; __syncthreads();

    float sum = 0.f;
#pragma unroll
    for (int r = 0; r < 4; r++) { v[r] = __expf(v[r] - mx); sum += v[r]; }
    red[t] = sum; __syncthreads();
    for (int s = 128; s > 0; s >>= 1) { if (t < s) red[t] += red[t + s]; __syncthreads(); }
    float inv = 1.0f / red[0];
#pragma unroll
    for (int r = 0; r < 4; r++)
        split_store(v[r] * inv, g_sim_hi, g_sim_lo, (size_t)i * NN + t + r * 256);
}

// ---------------------------------------------------------------------------
// K1: weights[n, kio] = sum_d E[n,d] * Wp[d, kio]
// ---------------------------------------------------------------------------
__global__ __launch_bounds__(256) void weights_kernel(const float* __restrict__ E,
                                                      const float* __restrict__ Wp) {
    const int t = threadIdx.x;
    const int kio = blockIdx.x * 256 + t;
    const int n0 = blockIdx.y * 128;

    float w[EMB];
#pragma unroll
    for (int d = 0; d < EMB; d++) w[d] = Wp[d * KIO + kio];   // coalesced

    __shared__ float Es[128][20];
#pragma unroll
    for (int l = 0; l < 2; l++) {
        int idx4 = t + l * 256;
        int r = idx4 >> 2, q4 = (idx4 & 3) * 4;
        *reinterpret_cast<float4*>(&Es[r][q4]) =
            *reinterpret_cast<const float4*>(&E[(n0 + r) * EMB + q4]);
    }
    __syncthreads();

    float* outp = g_w + (size_t)n0 * KIO + kio;
#pragma unroll 4
    for (int nn = 0; nn < 128; nn++) {
        float4 e0 = *reinterpret_cast<const float4*>(&Es[nn][0]);
        float4 e1 = *reinterpret_cast<const float4*>(&Es[nn][4]);
        float4 e2 = *reinterpret_cast<const float4*>(&Es[nn][8]);
        float4 e3 = *reinterpret_cast<const float4*>(&Es[nn][12]);
        float a0 = e0.x * w[0] + e0.y * w[1] + e0.z * w[2] + e0.w * w[3]
                 + e1.x * w[4] + e1.y * w[5] + e1.z * w[6] + e1.w * w[7];
        float a1 = e2.x * w[8] + e2.y * w[9] + e2.z * w[10] + e2.w * w[11]
                 + e3.x * w[12] + e3.y * w[13] + e3.z * w[14] + e3.w * w[15];
        outp[(size_t)nn * KIO] = a0 + a1;
    }
}

// K1b: bias[n,o] = sum_d E[n,d] * bp[d,o]
__global__ __launch_bounds__(256) void bias_kernel(const float* __restrict__ E,
                                                   const float* __restrict__ bp) {
    int idx = blockIdx.x * 256 + threadIdx.x;       // 65536
    int n = idx >> 6, o = idx & 63;
    float acc = 0.f;
#pragma unroll
    for (int d = 0; d < EMB; d++) acc += E[n * EMB + d] * bp[d * DOUT + o];
    g_bias[idx] = acc;
}

// ---------------------------------------------------------------------------
// K2: e[b,i,j] = exp(-sum_d |pa[b,i,d]-pa[b,j,d]|) -> bf16 hi/lo.
// SYMMETRIC: only upper-tri 64x64 tiles (ti<=tj); transposed copy via smem.
// Also emits per-tile row/col partial sums into g_part (no re-read for S).
// grid (136 tiles, 8 b), 256 threads.
// ---------------------------------------------------------------------------
__global__ __launch_bounds__(256) void e_kernel(const float* __restrict__ pa) {
    const int b = blockIdx.y;
    // map linear tile index -> (ti, tj) upper triangle, ti<=tj
    int rem = blockIdx.x, ti = 0;
    while (rem >= 16 - ti) { rem -= 16 - ti; ti++; }
    const int tjt = ti + rem;
    const int i0 = ti * 64, j0 = tjt * 64;
    const int t = threadIdx.x;
    const int tj = t & 63, tig = t >> 6;          // column, row-group

    __shared__ float paI[64][20];
    __shared__ float paJ[64][20];
    __shared__ float vS[64][65];                  // fp32 tile for transpose+sums
    __shared__ float cpS[4][64];                  // col-sum partials
    __shared__ float rpS[4][64];                  // row-sum partials

    const float* paB = pa + (size_t)b * NN * DPE;
    {
        int r = t >> 2, q4 = (t & 3) * 4;         // 256 float4s per tile
        *reinterpret_cast<float4*>(&paI[r][q4]) =
            *reinterpret_cast<const float4*>(&paB[(i0 + r) * DPE + q4]);
        *reinterpret_cast<float4*>(&paJ[r][q4]) =
            *reinterpret_cast<const float4*>(&paB[(j0 + r) * DPE + q4]);
    }
    __syncthreads();

    float pj[16];
#pragma unroll
    for (int q = 0; q < 4; q++) {
        float4 v = *reinterpret_cast<const float4*>(&paJ[tj][q * 4]);
        pj[q * 4 + 0] = v.x; pj[q * 4 + 1] = v.y; pj[q * 4 + 2] = v.z; pj[q * 4 + 3] = v.w;
    }

    __nv_bfloat16* outHi = g_e_hi + ((size_t)b * NN + i0) * NN + j0;
    __nv_bfloat16* outLo = g_e_lo + ((size_t)b * NN + i0) * NN + j0;
    float colPart = 0.f;
#pragma unroll 4
    for (int s = 0; s < 16; s++) {
        int i = tig * 16 + s;
        float4 p0 = *reinterpret_cast<const float4*>(&paI[i][0]);
        float4 p1 = *reinterpret_cast<const float4*>(&paI[i][4]);
        float4 p2 = *reinterpret_cast<const float4*>(&paI[i][8]);
        float4 p3 = *reinterpret_cast<const float4*>(&paI[i][12]);
        float a0 = fabsf(p0.x - pj[0])  + fabsf(p1.x - pj[4])
                 + fabsf(p2.x - pj[8])  + fabsf(p3.x - pj[12]);
        float a1 = fabsf(p0.y - pj[1])  + fabsf(p1.y - pj[5])
                 + fabsf(p2.y - pj[9])  + fabsf(p3.y - pj[13]);
        float a2 = fabsf(p0.z - pj[2])  + fabsf(p1.z - pj[6])
                 + fabsf(p2.z - pj[10]) + fabsf(p3.z - pj[14]);
        float a3 = fabsf(p0.w - pj[3])  + fabsf(p1.w - pj[7])
                 + fabsf(p2.w - pj[11]) + fabsf(p3.w - pj[15]);
        float v = __expf(-((a0 + a1) + (a2 + a3)));
        vS[i][tj] = v;
        colPart += v;
        __nv_bfloat16 h = __float2bfloat16(v);
        outHi[(size_t)i * NN + tj] = h;
        outLo[(size_t)i * NN + tj] = __float2bfloat16(v - __bfloat162float(h));
    }
    cpS[tig][tj] = colPart;
    __syncthreads();

    // row-sum partials: thread (qq, r) sums 16 columns of row r (stride-65, conflict-free)
    {
        int r = t & 63, qq = t >> 6;
        float s = 0.f;
#pragma unroll
        for (int c = 0; c < 16; c++) s += vS[r][qq * 16 + c];
        rpS[qq][r] = s;
    }
    __syncthreads();

    if (t < 64) {
        float rowP = rpS[0][t] + rpS[1][t] + rpS[2][t] + rpS[3][t];
        g_part[((size_t)b * NN + i0 + t) * 16 + tjt] = rowP;
    } else if (t < 128) {
        int c = t - 64;
        if (ti != tjt) {
            float colP = cpS[0][c] + cpS[1][c] + cpS[2][c] + cpS[3][c];
            g_part[((size_t)b * NN + j0 + c) * 16 + ti] = colP;
        }
    }

    // transposed copy for off-diagonal tiles: e[j0+r2][i0+tj] = vS[tj][r2]
    if (ti != tjt) {
        __nv_bfloat16* tHi = g_e_hi + ((size_t)b * NN + j0) * NN + i0;
        __nv_bfloat16* tLo = g_e_lo + ((size_t)b * NN + j0) * NN + i0;
#pragma unroll 4
        for (int s = 0; s < 16; s++) {
            int r2 = tig * 16 + s;
            float v = vS[tj][r2];
            __nv_bfloat16 h = __float2bfloat16(v);
            tHi[(size_t)r2 * NN + tj] = h;
            tLo[(size_t)r2 * NN + tj] = __float2bfloat16(v - __bfloat162float(h));
        }
    }
}

// K3: Sinv[row] = 1 / sum_k part[row][k]   (16 partials per row)
__global__ __launch_bounds__(256) void sinv_kernel() {
    int row = blockIdx.x * 256 + threadIdx.x;   // 8192
    const float* p = g_part + (size_t)row * 16;
    float s = 0.f;
#pragma unroll
    for (int k = 0; k < 16; k++) s += p[k];
    g_Sinv[row] = 1.0f / s;
}

// K3b: xs[b,c,d] = x[b,c,d] * Sinv[b,c]  ->  bf16 hi/lo
__global__ __launch_bounds__(256) void xs_kernel(const float* __restrict__ x) {
    int idx4 = blockIdx.x * 256 + threadIdx.x;       // 131072 float4s
    float4 v = *reinterpret_cast<const float4*>(&x[(size_t)idx4 * 4]);
    int b = idx4 >> 14;
    int c = (idx4 >> 4) & 1023;
    float s = g_Sinv[b * NN + c];
    v.x *= s; v.y *= s; v.z *= s; v.w *= s;
    __nv_bfloat162 h0 = __floats2bfloat162_rn(v.x, v.y);
    __nv_bfloat162 h1 = __floats2bfloat162_rn(v.z, v.w);
    float2 hf0 = __bfloat1622float2(h0);
    float2 hf1 = __bfloat1622float2(h1);
    __nv_bfloat162 l0 = __floats2bfloat162_rn(v.x - hf0.x, v.y - hf0.y);
    __nv_bfloat162 l1 = __floats2bfloat162_rn(v.z - hf1.x, v.w - hf1.y);
    *reinterpret_cast<__nv_bfloat162*>(&g_xs_hi[(size_t)idx4 * 4]) = h0;
    *reinterpret_cast<__nv_bfloat162*>(&g_xs_hi[(size_t)idx4 * 4 + 2]) = h1;
    *reinterpret_cast<__nv_bfloat162*>(&g_xs_lo[(size_t)idx4 * 4]) = l0;
    *reinterpret_cast<__nv_bfloat162*>(&g_xs_lo[(size_t)idx4 * 4 + 2]) = l1;
}

// ---------------------------------------------------------------------------
// K4: sxT[m][b][d] = sum_c e[b,m,c] * xs[b,c,d]  via bf16 mma (3-pass split)
// 2-stage cp.async pipeline, BK=32.  grid (16 m-tiles, 8 b)
// ---------------------------------------------------------------------------
__global__ __launch_bounds__(128) void sx_mma_kernel() {
    const int b = blockIdx.y, m0 = blockIdx.x * 64;
    const int t = threadIdx.x;
    const int warp = t >> 5, lane = t & 31;
    const int g = lane >> 2, tg = lane & 3;

    __shared__ __nv_bfloat16 Ah[2][64][40], Al[2][64][40];
    __shared__ __nv_bfloat16 Bh[2][32][72], Bl[2][32][72];

    const __nv_bfloat16* eHi = g_e_hi + ((size_t)b * NN + m0) * NN;
    const __nv_bfloat16* eLo = g_e_lo + ((size_t)b * NN + m0) * NN;
    const __nv_bfloat16* xHi = g_xs_hi + (size_t)b * NN * DIN;
    const __nv_bfloat16* xLo = g_xs_lo + (size_t)b * NN * DIN;

    float acc[8][4] = {};
    const int lrow = lane & 15;
    const int lcol = (lane & 16) >> 1;

    auto issue = [&](int st, int c0) {
#pragma unroll
        for (int l = 0; l < 2; l++) {
            int idx = t + l * 128;
            int r = idx >> 2, q = (idx & 3) * 8;     // A: 64 rows x 4 quads
            cpa16(&Ah[st][r][q], &eHi[(size_t)r * NN + c0 + q]);
            cpa16(&Al[st][r][q], &eLo[(size_t)r * NN + c0 + q]);
        }
#pragma unroll
        for (int l = 0; l < 2; l++) {
            int idx = t + l * 128;
            int r = idx >> 3, q = (idx & 7) * 8;     // B: 32 rows x 8 quads
            cpa16(&Bh[st][r][q], &xHi[(size_t)(c0 + r) * DIN + q]);
            cpa16(&Bl[st][r][q], &xLo[(size_t)(c0 + r) * DIN + q]);
        }
    };

    issue(0, 0); CP_COMMIT();
    for (int it = 0; it < 32; it++) {
        int cur = it & 1;
        if (it < 31) { issue(cur ^ 1, (it + 1) * 32); CP_COMMIT(); CP_WAIT1(); }
        else CP_WAIT0();
        __syncthreads();

#pragma unroll
        for (int k16 = 0; k16 < 2; k16++) {
            unsigned A_h[4], A_l[4];
            ldsm_x4(A_h, s2u(&Ah[cur][warp * 16 + lrow][k16 * 16 + lcol]));
            ldsm_x4(A_l, s2u(&Al[cur][warp * 16 + lrow][k16 * 16 + lcol]));
            unsigned Bfh[8][2], Bfl[8][2];
#pragma unroll
            for (int nb = 0; nb < 4; nb++) {
                unsigned tmp[4];
                ldsm_x4_t(tmp, s2u(&Bh[cur][k16 * 16 + lrow][nb * 16 + lcol]));
                Bfh[nb * 2][0] = tmp[0]; Bfh[nb * 2][1] = tmp[1];
                Bfh[nb * 2 + 1][0] = tmp[2]; Bfh[nb * 2 + 1][1] = tmp[3];
                ldsm_x4_t(tmp, s2u(&Bl[cur][k16 * 16 + lrow][nb * 16 + lcol]));
                Bfl[nb * 2][0] = tmp[0]; Bfl[nb * 2][1] = tmp[1];
                Bfl[nb * 2 + 1][0] = tmp[2]; Bfl[nb * 2 + 1][1] = tmp[3];
            }
#pragma unroll
            for (int f = 0; f < 8; f++) {
                mma16816(acc[f], A_h, Bfh[f][0], Bfh[f][1]);
                mma16816(acc[f], A_h, Bfl[f][0], Bfl[f][1]);
                mma16816(acc[f], A_l, Bfh[f][0], Bfh[f][1]);
            }
        }
        __syncthreads();
    }

    // epilogue: fp32 + bf16 hi/lo split for s1's B operand
    const int m_lo = m0 + warp * 16 + g;
#pragma unroll
    for (int f = 0; f < 8; f++) {
        int col = f * 8 + tg * 2;
#pragma unroll
        for (int h = 0; h < 2; h++) {
            int m = m_lo + h * 8;
            float vx = acc[f][h * 2], vy = acc[f][h * 2 + 1];
            size_t o = ((size_t)m * BB + b) * DIN + col;
            *reinterpret_cast<float2*>(&g_sxT[o]) = make_float2(vx, vy);
            __nv_bfloat162 hv = __floats2bfloat162_rn(vx, vy);
            float2 hf = __bfloat1622float2(hv);
            __nv_bfloat162 lv = __floats2bfloat162_rn(vx - hf.x, vy - hf.y);
            *reinterpret_cast<__nv_bfloat162*>(&g_sxT_hi[o]) = hv;
            *reinterpret_cast<__nv_bfloat162*>(&g_sxT_lo[o]) = lv;
        }
    }
}

// ---------------------------------------------------------------------------
// K5: s1[n][bd] = sum_m sim[n,m] * sxT[m][bd]  via bf16 mma (3-pass split)
// 2-stage cp.async pipeline.  grid (16 n-tiles, 8 bd-tiles)
// ---------------------------------------------------------------------------
__global__ __launch_bounds__(128) void s1_mma_kernel() {
    const int n0 = blockIdx.x * 64, bd0 = blockIdx.y * 64;
    const int t = threadIdx.x;
    const int warp = t >> 5, lane = t & 31;
    const int g = lane >> 2, tg = lane & 3;

    __shared__ __nv_bfloat16 Ah[2][64][40], Al[2][64][40];
    __shared__ __nv_bfloat16 Bh[2][32][72], Bl[2][32][72];

    const __nv_bfloat16* aHi = g_sim_hi + (size_t)n0 * NN;
    const __nv_bfloat16* aLo = g_sim_lo + (size_t)n0 * NN;

    float acc[8][4] = {};
    const int lrow = lane & 15;
    const int lcol = (lane & 16) >> 1;

    auto issue = [&](int st, int c0) {
#pragma unroll
        for (int l = 0; l < 2; l++) {
            int idx = t + l * 128;
            int r = idx >> 2, q = (idx & 3) * 8;
            cpa16(&Ah[st][r][q], &aHi[(size_t)r * NN + c0 + q]);
            cpa16(&Al[st][r][q], &aLo[(size_t)r * NN + c0 + q]);
        }
#pragma unroll
        for (int l = 0; l < 2; l++) {
            int idx = t + l * 128;
            int r = idx >> 3, q = (idx & 7) * 8;
            cpa16(&Bh[st][r][q], &g_sxT_hi[(size_t)(c0 + r) * (BB * DIN) + bd0 + q]);
            cpa16(&Bl[st][r][q], &g_sxT_lo[(size_t)(c0 + r) * (BB * DIN) + bd0 + q]);
        }
    };

    issue(0, 0); CP_COMMIT();
    for (int it = 0; it < 32; it++) {
        int cur = it & 1;
        if (it < 31) { issue(cur ^ 1, (it + 1) * 32); CP_COMMIT(); CP_WAIT1(); }
        else CP_WAIT0();
        __syncthreads();

#pragma unroll
        for (int k16 = 0; k16 < 2; k16++) {
            unsigned A_h[4], A_l[4];
            ldsm_x4(A_h, s2u(&Ah[cur][warp * 16 + lrow][k16 * 16 + lcol]));
            ldsm_x4(A_l, s2u(&Al[cur][warp * 16 + lrow][k16 * 16 + lcol]));
            unsigned Bfh[8][2], Bfl[8][2];
#pragma unroll
            for (int nb = 0; nb < 4; nb++) {
                unsigned tmp[4];
                ldsm_x4_t(tmp, s2u(&Bh[cur][k16 * 16 + lrow][nb * 16 + lcol]));
                Bfh[nb * 2][0] = tmp[0]; Bfh[nb * 2][1] = tmp[1];
                Bfh[nb * 2 + 1][0] = tmp[2]; Bfh[nb * 2 + 1][1] = tmp[3];
                ldsm_x4_t(tmp, s2u(&Bl[cur][k16 * 16 + lrow][nb * 16 + lcol]));
                Bfl[nb * 2][0] = tmp[0]; Bfl[nb * 2][1] = tmp[1];
                Bfl[nb * 2 + 1][0] = tmp[2]; Bfl[nb * 2 + 1][1] = tmp[3];
            }
#pragma unroll
            for (int f = 0; f < 8; f++) {
                mma16816(acc[f], A_h, Bfh[f][0], Bfh[f][1]);
                mma16816(acc[f], A_h, Bfl[f][0], Bfl[f][1]);
                mma16816(acc[f], A_l, Bfh[f][0], Bfh[f][1]);
            }
        }
        __syncthreads();
    }

    const int n_lo = n0 + warp * 16 + g;
#pragma unroll
    for (int f = 0; f < 8; f++) {
        int col = bd0 + f * 8 + tg * 2;
#pragma unroll
        for (int h = 0; h < 2; h++) {
            int n = n_lo + h * 8;
            *reinterpret_cast<float2*>(&g_s1[(size_t)n * (BB * DIN) + col]) =
                make_float2(acc[f][h * 2], acc[f][h * 2 + 1]);
        }
    }
}

// ---------------------------------------------------------------------------
// K6: out[b,n,o] = bias[n,o] + sum_i sx[n,b,i] w[n,0,i,o] + sum_i s1[n,b,i] w[n,1,i,o]
// ---------------------------------------------------------------------------
__global__ __launch_bounds__(256) void out_kernel(float* __restrict__ out) {
    const int n = blockIdx.x, t = threadIdx.x;
    __shared__ float wS[KIO];            // 32 KB
    __shared__ float xgS[2][BB][DIN];    // 4 KB
    __shared__ float bS[DOUT];
    __shared__ float red[128][4];        // 2 KB
    const float* wp = g_w + (size_t)n * KIO;
#pragma unroll
    for (int l = 0; l < 8; l++) {
        int idx4 = t + l * 256;
        *reinterpret_cast<float4*>(&wS[idx4 * 4]) =
            *reinterpret_cast<const float4*>(&wp[idx4 * 4]);
    }
    {
        float* xgFlat = &xgS[0][0][0];
        const float* src = (t < 128) ? (g_sxT + (size_t)n * (BB * DIN) + t * 4)
                                     : (g_s1  + (size_t)n * (BB * DIN) + (t - 128) * 4);
        *reinterpret_cast<float4*>(&xgFlat[t * 4]) =
            *reinterpret_cast<const float4*>(src);
    }
    if (t < DOUT) bS[t] = g_bias[n * DOUT + t];
    __syncthreads();

    const int half = t >> 7;
    const int q = t & 127;
    const int b = q >> 4, o4 = (q & 15) * 4;
    float4 acc = make_float4(0.f, 0.f, 0.f, 0.f);
    const int i0 = half * 32;
#pragma unroll 8
    for (int ii = 0; ii < 32; ii++) {
        int i = i0 + ii;
        float4 w0 = *reinterpret_cast<const float4*>(&wS[i * 64 + o4]);
        float4 w1 = *reinterpret_cast<const float4*>(&wS[4096 + i * 64 + o4]);
        float x0 = xgS[0][b][i];
        float x1 = xgS[1][b][i];
        acc.x += x0 * w0.x + x1 * w1.x;
        acc.y += x0 * w0.y + x1 * w1.y;
        acc.z += x0 * w0.z + x1 * w1.z;
        acc.w += x0 * w0.w + x1 * w1.w;
    }
    if (half == 1) *reinterpret_cast<float4*>(&red[q][0]) = acc;
    __syncthreads();
    if (half == 0) {
        float4 r = *reinterpret_cast<const float4*>(&red[q][0]);
        float4 v;
        v.x = acc.x + r.x + bS[o4 + 0];
        v.y = acc.y + r.y + bS[o4 + 1];
        v.z = acc.z + r.z + bS[o4 + 2];
        v.w = acc.w + r.w + bS[o4 + 3];
        *reinterpret_cast<float4*>(&out[((size_t)b * NN + n) * DOUT + o4]) = v;
    }
}

// ---------------------------------------------------------------------------
extern "C" void kernel_launch(void* const* d_in, const int* in_sizes, int n_in,
                              void* d_out, int out_size) {
    const float* x    = (const float*)d_in[0];   // [8,1024,64]
    const float* E    = (const float*)d_in[1];   // [1024,16]
    const float* pa   = (const float*)d_in[2];   // [8,1024,16]
    const float* Wp   = (const float*)d_in[3];   // [16,2,64,64]
    const float* bp   = (const float*)d_in[4];   // [16,64]
    float* out = (float*)d_out;                  // [8,1024,64]

    sim_kernel<<<NN, 256>>>(E);
    weights_kernel<<<dim3(KIO / 256, NN / 128), 256>>>(E, Wp);
    bias_kernel<<<NN * DOUT / 256, 256>>>(E, bp);
    e_kernel<<<dim3(136, BB), 256>>>(pa);
    sinv_kernel<<<BB * NN / 256, 256>>>();
    xs_kernel<<<BB * NN * DIN / 1024, 256>>>(x);
    sx_mma_kernel<<<dim3(NN / 64, BB), 128>>>();
    s1_mma_kernel<<<dim3(NN / 64, BB * DIN / 64), 128>>>();
    out_kernel<<<NN, 256>>>(out);
}

// round 10
// speedup vs baseline: 2.2231x; 1.0155x over previous
#include <cuda_runtime.h>
#include <cuda_bf16.h>
#include <cstdint>

#define NN 1024
#define BB 8
#define DIN 64
#define DOUT 64
#define EMB 16
#define DPE 16
#define KIO 8192   // 2*64*64

// ---- device scratch (no allocations allowed) ----
__device__ __nv_bfloat16 g_e_hi[(size_t)BB * NN * NN];   // 16 MB
__device__ __nv_bfloat16 g_e_lo[(size_t)BB * NN * NN];   // 16 MB
__device__ __nv_bfloat16 g_sim_hi[NN * NN];              // 2 MB
__device__ __nv_bfloat16 g_sim_lo[NN * NN];              // 2 MB
__device__ __nv_bfloat16 g_xs_hi[BB * NN * DIN];         // 1 MB  (x*Sinv)
__device__ __nv_bfloat16 g_xs_lo[BB * NN * DIN];         // 1 MB
__device__ __nv_bfloat16 g_sxT_hi[NN * BB * DIN];        // 1 MB
__device__ __nv_bfloat16 g_sxT_lo[NN * BB * DIN];        // 1 MB
__device__ float g_w[NN * KIO];           // 32 MB  weights[n][k][i][o]
__device__ float g_bias[NN * DOUT];       // 256 KB
__device__ float g_part[BB * NN * 16];    // 512 KB row-sum partials
__device__ float g_Sinv[BB * NN];         // 32 KB
__device__ float g_sxT[NN * BB * DIN];    // 2 MB
__device__ float g_s1[NN * BB * DIN];     // 2 MB

// ---------- helpers ----------
static __device__ __forceinline__ unsigned int s2u(const void* p) {
    return (unsigned int)__cvta_generic_to_shared(p);
}
static __device__ __forceinline__ void ldsm_x4(unsigned r[4], unsigned int addr) {
    asm volatile("ldmatrix.sync.aligned.m8n8.x4.shared.b16 {%0,%1,%2,%3}, [%4];"
        : "=r"(r[0]), "=r"(r[1]), "=r"(r[2]), "=r"(r[3]) : "r"(addr));
}
static __device__ __forceinline__ void ldsm_x4_t(unsigned r[4], unsigned int addr) {
    asm volatile("ldmatrix.sync.aligned.m8n8.x4.trans.shared.b16 {%0,%1,%2,%3}, [%4];"
        : "=r"(r[0]), "=r"(r[1]), "=r"(r[2]), "=r"(r[3]) : "r"(addr));
}
static __device__ __forceinline__ void mma16816(float c[4], const unsigned a[4], const unsigned b0, const unsigned b1) {
    asm volatile("mma.sync.aligned.m16n8k16.row.col.f32.bf16.bf16.f32 "
        "{%0,%1,%2,%3}, {%4,%5,%6,%7}, {%8,%9}, {%0,%1,%2,%3};"
        : "+f"(c[0]), "+f"(c[1]), "+f"(c[2]), "+f"(c[3])
        : "r"(a[0]), "r"(a[1]), "r"(a[2]), "r"(a[3]), "r"(b0), "r"(b1));
}
static __device__ __forceinline__ void cpa16(void* dst, const void* src) {
    unsigned int d = s2u(dst);
    asm volatile("cp.async.ca.shared.global [%0], [%1], 16;" :: "r"(d), "l"(src));
}
#define CP_COMMIT() asm volatile("cp.async.commit_group;" ::: "memory")
#define CP_WAIT1()  asm volatile("cp.async.wait_group 1;" ::: "memory")
#define CP_WAIT0()  asm volatile("cp.async.wait_group 0;" ::: "memory")

static __device__ __forceinline__ void split_store(float v, __nv_bfloat16* hi, __nv_bfloat16* lo, size_t off) {
    __nv_bfloat16 h = __float2bfloat16(v);
    hi[off] = h;
    lo[off] = __float2bfloat16(v - __bfloat162float(h));
}
// pack pair (v0 -> low element, v1 -> high element) as hi/lo bf16x2 words
static __device__ __forceinline__ void split_pair(float v0, float v1,
                                                  __nv_bfloat162& hv, __nv_bfloat162& lv) {
    hv = __floats2bfloat162_rn(v0, v1);
    float2 hf = __bfloat1622float2(hv);
    lv = __floats2bfloat162_rn(v0 - hf.x, v1 - hf.y);
}

// ---------------------------------------------------------------------------
// K0: sim = softmax(relu(E E^T), axis=1) -> bf16 hi/lo.  one block per row
// ---------------------------------------------------------------------------
__global__ __launch_bounds__(256) void sim_kernel(const float* __restrict__ E) {
    const int i = blockIdx.x;
    const int t = threadIdx.x;
    __shared__ float Ei[EMB];
    __shared__ float red[256];
    if (t < EMB) Ei[t] = E[i * EMB + t];
    __syncthreads();

    float v[4];
    float mx = -1e30f;
#pragma unroll
    for (int r = 0; r < 4; r++) {
        int j = t + r * 256;
        const float4* Ej = reinterpret_cast<const float4*>(E + j * EMB);
        float acc = 0.f;
#pragma unroll
        for (int q = 0; q < 4; q++) {
            float4 e4 = Ej[q];
            acc += Ei[q * 4 + 0] * e4.x + Ei[q * 4 + 1] * e4.y
                 + Ei[q * 4 + 2] * e4.z + Ei[q * 4 + 3] * e4.w;
        }
        acc = fmaxf(acc, 0.f);
        v[r] = acc;
        mx = fmaxf(mx, acc);
    }
    red[t] = mx; __syncthreads();
    for (int s = 128; s > 0; s >>= 1) { if (t < s) red[t] = fmaxf(red[t], red[t + s]); __syncthreads(); }
    mx = red[0]; __syncthreads();

    float sum = 0.f;
#pragma unroll
    for (int r = 0; r < 4; r++) { v[r] = __expf(v[r] - mx); sum += v[r]; }
    red[t] = sum; __syncthreads();
    for (int s = 128; s > 0; s >>= 1) { if (t < s) red[t] += red[t + s]; __syncthreads(); }
    float inv = 1.0f / red[0];
#pragma unroll
    for (int r = 0; r < 4; r++)
        split_store(v[r] * inv, g_sim_hi, g_sim_lo, (size_t)i * NN + t + r * 256);
}

// ---------------------------------------------------------------------------
// K1: weights[n, kio] = sum_d E[n,d] * Wp[d, kio]
// ---------------------------------------------------------------------------
__global__ __launch_bounds__(256) void weights_kernel(const float* __restrict__ E,
                                                      const float* __restrict__ Wp) {
    const int t = threadIdx.x;
    const int kio = blockIdx.x * 256 + t;
    const int n0 = blockIdx.y * 128;

    float w[EMB];
#pragma unroll
    for (int d = 0; d < EMB; d++) w[d] = Wp[d * KIO + kio];   // coalesced

    __shared__ float Es[128][20];
#pragma unroll
    for (int l = 0; l < 2; l++) {
        int idx4 = t + l * 256;
        int r = idx4 >> 2, q4 = (idx4 & 3) * 4;
        *reinterpret_cast<float4*>(&Es[r][q4]) =
            *reinterpret_cast<const float4*>(&E[(n0 + r) * EMB + q4]);
    }
    __syncthreads();

    float* outp = g_w + (size_t)n0 * KIO + kio;
#pragma unroll 4
    for (int nn = 0; nn < 128; nn++) {
        float4 e0 = *reinterpret_cast<const float4*>(&Es[nn][0]);
        float4 e1 = *reinterpret_cast<const float4*>(&Es[nn][4]);
        float4 e2 = *reinterpret_cast<const float4*>(&Es[nn][8]);
        float4 e3 = *reinterpret_cast<const float4*>(&Es[nn][12]);
        float a0 = e0.x * w[0] + e0.y * w[1] + e0.z * w[2] + e0.w * w[3]
                 + e1.x * w[4] + e1.y * w[5] + e1.z * w[6] + e1.w * w[7];
        float a1 = e2.x * w[8] + e2.y * w[9] + e2.z * w[10] + e2.w * w[11]
                 + e3.x * w[12] + e3.y * w[13] + e3.z * w[14] + e3.w * w[15];
        outp[(size_t)nn * KIO] = a0 + a1;
    }
}

// K1b: bias[n,o] = sum_d E[n,d] * bp[d,o]
__global__ __launch_bounds__(256) void bias_kernel(const float* __restrict__ E,
                                                   const float* __restrict__ bp) {
    int idx = blockIdx.x * 256 + threadIdx.x;       // 65536
    int n = idx >> 6, o = idx & 63;
    float acc = 0.f;
#pragma unroll
    for (int d = 0; d < EMB; d++) acc += E[n * EMB + d] * bp[d * DOUT + o];
    g_bias[idx] = acc;
}

// ---------------------------------------------------------------------------
// K2: e[b,i,j] = exp(-sum_d |pa[b,i,d]-pa[b,j,d]|) -> bf16 hi/lo, packed x2 stores.
// Upper-tri tiles only; transposed tile + row/col partials via smem.
// Thread layout: 32 column-pairs x 8 row-groups (8 rows each).
// ---------------------------------------------------------------------------
__global__ __launch_bounds__(256) void e_kernel(const float* __restrict__ pa) {
    const int b = blockIdx.y;
    int rem = blockIdx.x, ti = 0;
    while (rem >= 16 - ti) { rem -= 16 - ti; ti++; }
    const int tjt = ti + rem;
    const int i0 = ti * 64, j0 = tjt * 64;
    const int t = threadIdx.x;
    const int cp = t & 31, rg = t >> 5;
    const int c0 = cp * 2;

    __shared__ float paI[64][20];
    __shared__ float paJ[64][20];
    __shared__ float vS[64][65];
    __shared__ float cpS[8][64];
    __shared__ float rpS[4][64];

    const float* paB = pa + (size_t)b * NN * DPE;
    {
        int r = t >> 2, q4 = (t & 3) * 4;         // 256 float4s each
        *reinterpret_cast<float4*>(&paI[r][q4]) =
            *reinterpret_cast<const float4*>(&paB[(i0 + r) * DPE + q4]);
        *reinterpret_cast<float4*>(&paJ[r][q4]) =
            *reinterpret_cast<const float4*>(&paB[(j0 + r) * DPE + q4]);
    }
    __syncthreads();

    float pj0[16], pj1[16];
#pragma unroll
    for (int q = 0; q < 4; q++) {
        float4 u = *reinterpret_cast<const float4*>(&paJ[c0][q * 4]);
        pj0[q * 4 + 0] = u.x; pj0[q * 4 + 1] = u.y; pj0[q * 4 + 2] = u.z; pj0[q * 4 + 3] = u.w;
        float4 w = *reinterpret_cast<const float4*>(&paJ[c0 + 1][q * 4]);
        pj1[q * 4 + 0] = w.x; pj1[q * 4 + 1] = w.y; pj1[q * 4 + 2] = w.z; pj1[q * 4 + 3] = w.w;
    }

    const unsigned baseD = (unsigned)((b * NN + i0) * NN + j0);
    float cps0 = 0.f, cps1 = 0.f;
#pragma unroll
    for (int s = 0; s < 8; s++) {
        int i = rg * 8 + s;
        float4 p0 = *reinterpret_cast<const float4*>(&paI[i][0]);
        float4 p1 = *reinterpret_cast<const float4*>(&paI[i][4]);
        float4 p2 = *reinterpret_cast<const float4*>(&paI[i][8]);
        float4 p3 = *reinterpret_cast<const float4*>(&paI[i][12]);
        float d0 = (((fabsf(p0.x - pj0[0])  + fabsf(p0.y - pj0[1]))
                  +  (fabsf(p0.z - pj0[2])  + fabsf(p0.w - pj0[3])))
                 +  ((fabsf(p1.x - pj0[4])  + fabsf(p1.y - pj0[5]))
                  +  (fabsf(p1.z - pj0[6])  + fabsf(p1.w - pj0[7]))))
                 + (((fabsf(p2.x - pj0[8])  + fabsf(p2.y - pj0[9]))
                  +  (fabsf(p2.z - pj0[10]) + fabsf(p2.w - pj0[11])))
                 +  ((fabsf(p3.x - pj0[12]) + fabsf(p3.y - pj0[13]))
                  +  (fabsf(p3.z - pj0[14]) + fabsf(p3.w - pj0[15]))));
        float d1 = (((fabsf(p0.x - pj1[0])  + fabsf(p0.y - pj1[1]))
                  +  (fabsf(p0.z - pj1[2])  + fabsf(p0.w - pj1[3])))
                 +  ((fabsf(p1.x - pj1[4])  + fabsf(p1.y - pj1[5]))
                  +  (fabsf(p1.z - pj1[6])  + fabsf(p1.w - pj1[7]))))
                 + (((fabsf(p2.x - pj1[8])  + fabsf(p2.y - pj1[9]))
                  +  (fabsf(p2.z - pj1[10]) + fabsf(p2.w - pj1[11])))
                 +  ((fabsf(p3.x - pj1[12]) + fabsf(p3.y - pj1[13]))
                  +  (fabsf(p3.z - pj1[14]) + fabsf(p3.w - pj1[15]))));
        float v0 = __expf(-d0), v1 = __expf(-d1);
        vS[i][c0] = v0; vS[i][c0 + 1] = v1;
        cps0 += v0; cps1 += v1;
        __nv_bfloat162 hv, lv; split_pair(v0, v1, hv, lv);
        unsigned off = baseD + (unsigned)i * NN + c0;
        *reinterpret_cast<__nv_bfloat162*>(g_e_hi + off) = hv;
        *reinterpret_cast<__nv_bfloat162*>(g_e_lo + off) = lv;
    }
    cpS[rg][c0] = cps0; cpS[rg][c0 + 1] = cps1;
    __syncthreads();

    // row partials: thread (qq, r) sums 16 columns of row r
    {
        int r = t & 63, qq = t >> 6;
        float s = 0.f;
#pragma unroll
        for (int c = 0; c < 16; c++) s += vS[r][qq * 16 + c];
        rpS[qq][r] = s;
    }
    __syncthreads();

    if (t < 64) {
        float rowP = rpS[0][t] + rpS[1][t] + rpS[2][t] + rpS[3][t];
        g_part[((size_t)b * NN + i0 + t) * 16 + tjt] = rowP;
    } else if (t < 128 && ti != tjt) {
        int c = t - 64;
        float colP = 0.f;
#pragma unroll
        for (int q = 0; q < 8; q++) colP += cpS[q][c];
        g_part[((size_t)b * NN + j0 + c) * 16 + ti] = colP;
    }

    // transposed tile for off-diagonal: T[r2][c0..c0+1] = vS[c0..c0+1][r2]
    if (ti != tjt) {
        const unsigned baseT = (unsigned)((b * NN + j0) * NN + i0);
#pragma unroll
        for (int s = 0; s < 8; s++) {
            int r2 = rg * 8 + s;
            float v0 = vS[c0][r2], v1 = vS[c0 + 1][r2];
            __nv_bfloat162 hv, lv; split_pair(v0, v1, hv, lv);
            unsigned off = baseT + (unsigned)r2 * NN + c0;
            *reinterpret_cast<__nv_bfloat162*>(g_e_hi + off) = hv;
            *reinterpret_cast<__nv_bfloat162*>(g_e_lo + off) = lv;
        }
    }
}

// K3: Sinv[row] = 1 / sum_k part[row][k]
__global__ __launch_bounds__(256) void sinv_kernel() {
    int row = blockIdx.x * 256 + threadIdx.x;   // 8192
    const float* p = g_part + (size_t)row * 16;
    float s = 0.f;
#pragma unroll
    for (int k = 0; k < 16; k++) s += p[k];
    g_Sinv[row] = 1.0f / s;
}

// K3b: xs[b,c,d] = x[b,c,d] * Sinv[b,c]  ->  bf16 hi/lo
__global__ __launch_bounds__(256) void xs_kernel(const float* __restrict__ x) {
    int idx4 = blockIdx.x * 256 + threadIdx.x;       // 131072 float4s
    float4 v = *reinterpret_cast<const float4*>(&x[(size_t)idx4 * 4]);
    int b = idx4 >> 14;
    int c = (idx4 >> 4) & 1023;
    float s = g_Sinv[b * NN + c];
    v.x *= s; v.y *= s; v.z *= s; v.w *= s;
    __nv_bfloat162 h0, l0, h1, l1;
    split_pair(v.x, v.y, h0, l0);
    split_pair(v.z, v.w, h1, l1);
    *reinterpret_cast<__nv_bfloat162*>(&g_xs_hi[(size_t)idx4 * 4]) = h0;
    *reinterpret_cast<__nv_bfloat162*>(&g_xs_hi[(size_t)idx4 * 4 + 2]) = h1;
    *reinterpret_cast<__nv_bfloat162*>(&g_xs_lo[(size_t)idx4 * 4]) = l0;
    *reinterpret_cast<__nv_bfloat162*>(&g_xs_lo[(size_t)idx4 * 4 + 2]) = l1;
}

// ---------------------------------------------------------------------------
// K4: sxT[m][b][d] = sum_c e[b,m,c] * xs[b,c,d]  via bf16 mma (3-pass split)
// 3-stage cp.async ring, one __syncthreads per iter.  grid (16 m-tiles, 8 b)
// ---------------------------------------------------------------------------
__global__ __launch_bounds__(128) void sx_mma_kernel() {
    const int b = blockIdx.y, m0 = blockIdx.x * 64;
    const int t = threadIdx.x;
    const int warp = t >> 5, lane = t & 31;
    const int g = lane >> 2, tg = lane & 3;

    __shared__ __nv_bfloat16 Ah[3][64][40], Al[3][64][40];
    __shared__ __nv_bfloat16 Bh[3][32][72], Bl[3][32][72];

    const __nv_bfloat16* eHi = g_e_hi + ((size_t)b * NN + m0) * NN;
    const __nv_bfloat16* eLo = g_e_lo + ((size_t)b * NN + m0) * NN;
    const __nv_bfloat16* xHi = g_xs_hi + (size_t)b * NN * DIN;
    const __nv_bfloat16* xLo = g_xs_lo + (size_t)b * NN * DIN;

    float acc[8][4] = {};
    const int lrow = lane & 15;
    const int lcol = (lane & 16) >> 1;

    auto issue = [&](int st, int c0) {
#pragma unroll
        for (int l = 0; l < 2; l++) {
            int idx = t + l * 128;
            int r = idx >> 2, q = (idx & 3) * 8;     // A: 64 rows x 4 quads
            cpa16(&Ah[st][r][q], &eHi[(size_t)r * NN + c0 + q]);
            cpa16(&Al[st][r][q], &eLo[(size_t)r * NN + c0 + q]);
        }
#pragma unroll
        for (int l = 0; l < 2; l++) {
            int idx = t + l * 128;
            int r = idx >> 3, q = (idx & 7) * 8;     // B: 32 rows x 8 quads
            cpa16(&Bh[st][r][q], &xHi[(size_t)(c0 + r) * DIN + q]);
            cpa16(&Bl[st][r][q], &xLo[(size_t)(c0 + r) * DIN + q]);
        }
    };

    issue(0, 0); CP_COMMIT();
    issue(1, 32); CP_COMMIT();
    for (int it = 0; it < 32; it++) {
        int cur = it % 3;
        if (it < 31) CP_WAIT1(); else CP_WAIT0();
        __syncthreads();

#pragma unroll
        for (int k16 = 0; k16 < 2; k16++) {
            unsigned A_h[4], A_l[4];
            ldsm_x4(A_h, s2u(&Ah[cur][warp * 16 + lrow][k16 * 16 + lcol]));
            ldsm_x4(A_l, s2u(&Al[cur][warp * 16 + lrow][k16 * 16 + lcol]));
            unsigned Bfh[8][2], Bfl[8][2];
#pragma unroll
            for (int nb = 0; nb < 4; nb++) {
                unsigned tmp[4];
                ldsm_x4_t(tmp, s2u(&Bh[cur][k16 * 16 + lrow][nb * 16 + lcol]));
                Bfh[nb * 2][0] = tmp[0]; Bfh[nb * 2][1] = tmp[1];
                Bfh[nb * 2 + 1][0] = tmp[2]; Bfh[nb * 2 + 1][1] = tmp[3];
                ldsm_x4_t(tmp, s2u(&Bl[cur][k16 * 16 + lrow][nb * 16 + lcol]));
                Bfl[nb * 2][0] = tmp[0]; Bfl[nb * 2][1] = tmp[1];
                Bfl[nb * 2 + 1][0] = tmp[2]; Bfl[nb * 2 + 1][1] = tmp[3];
            }
#pragma unroll
            for (int f = 0; f < 8; f++) {
                mma16816(acc[f], A_h, Bfh[f][0], Bfh[f][1]);
                mma16816(acc[f], A_h, Bfl[f][0], Bfl[f][1]);
                mma16816(acc[f], A_l, Bfh[f][0], Bfh[f][1]);
            }
        }
        if (it + 2 < 32) { issue((it + 2) % 3, (it + 2) * 32); CP_COMMIT(); }
    }

    // epilogue: fp32 + bf16 hi/lo split for s1's B operand
    const int m_lo = m0 + warp * 16 + g;
#pragma unroll
    for (int f = 0; f < 8; f++) {
        int col = f * 8 + tg * 2;
#pragma unroll
        for (int h = 0; h < 2; h++) {
            int m = m_lo + h * 8;
            float vx = acc[f][h * 2], vy = acc[f][h * 2 + 1];
            size_t o = ((size_t)m * BB + b) * DIN + col;
            *reinterpret_cast<float2*>(&g_sxT[o]) = make_float2(vx, vy);
            __nv_bfloat162 hv, lv; split_pair(vx, vy, hv, lv);
            *reinterpret_cast<__nv_bfloat162*>(&g_sxT_hi[o]) = hv;
            *reinterpret_cast<__nv_bfloat162*>(&g_sxT_lo[o]) = lv;
        }
    }
}

// ---------------------------------------------------------------------------
// K5: s1[n][bd] = sum_m sim[n,m] * sxT[m][bd]  via bf16 mma (3-pass split)
// 3-stage cp.async ring.  grid (16 n-tiles, 8 bd-tiles)
// ---------------------------------------------------------------------------
__global__ __launch_bounds__(128) void s1_mma_kernel() {
    const int n0 = blockIdx.x * 64, bd0 = blockIdx.y * 64;
    const int t = threadIdx.x;
    const int warp = t >> 5, lane = t & 31;
    const int g = lane >> 2, tg = lane & 3;

    __shared__ __nv_bfloat16 Ah[3][64][40], Al[3][64][40];
    __shared__ __nv_bfloat16 Bh[3][32][72], Bl[3][32][72];

    const __nv_bfloat16* aHi = g_sim_hi + (size_t)n0 * NN;
    const __nv_bfloat16* aLo = g_sim_lo + (size_t)n0 * NN;

    float acc[8][4] = {};
    const int lrow = lane & 15;
    const int lcol = (lane & 16) >> 1;

    auto issue = [&](int st, int c0) {
#pragma unroll
        for (int l = 0; l < 2; l++) {
            int idx = t + l * 128;
            int r = idx >> 2, q = (idx & 3) * 8;
            cpa16(&Ah[st][r][q], &aHi[(size_t)r * NN + c0 + q]);
            cpa16(&Al[st][r][q], &aLo[(size_t)r * NN + c0 + q]);
        }
#pragma unroll
        for (int l = 0; l < 2; l++) {
            int idx = t + l * 128;
            int r = idx >> 3, q = (idx & 7) * 8;
            cpa16(&Bh[st][r][q], &g_sxT_hi[(size_t)(c0 + r) * (BB * DIN) + bd0 + q]);
            cpa16(&Bl[st][r][q], &g_sxT_lo[(size_t)(c0 + r) * (BB * DIN) + bd0 + q]);
        }
    };

    issue(0, 0); CP_COMMIT();
    issue(1, 32); CP_COMMIT();
    for (int it = 0; it < 32; it++) {
        int cur = it % 3;
        if (it < 31) CP_WAIT1(); else CP_WAIT0();
        __syncthreads();

#pragma unroll
        for (int k16 = 0; k16 < 2; k16++) {
            unsigned A_h[4], A_l[4];
            ldsm_x4(A_h, s2u(&Ah[cur][warp * 16 + lrow][k16 * 16 + lcol]));
            ldsm_x4(A_l, s2u(&Al[cur][warp * 16 + lrow][k16 * 16 + lcol]));
            unsigned Bfh[8][2], Bfl[8][2];
#pragma unroll
            for (int nb = 0; nb < 4; nb++) {
                unsigned tmp[4];
                ldsm_x4_t(tmp, s2u(&Bh[cur][k16 * 16 + lrow][nb * 16 + lcol]));
                Bfh[nb * 2][0] = tmp[0]; Bfh[nb * 2][1] = tmp[1];
                Bfh[nb * 2 + 1][0] = tmp[2]; Bfh[nb * 2 + 1][1] = tmp[3];
                ldsm_x4_t(tmp, s2u(&Bl[cur][k16 * 16 + lrow][nb * 16 + lcol]));
                Bfl[nb * 2][0] = tmp[0]; Bfl[nb * 2][1] = tmp[1];
                Bfl[nb * 2 + 1][0] = tmp[2]; Bfl[nb * 2 + 1][1] = tmp[3];
            }
#pragma unroll
            for (int f = 0; f < 8; f++) {
                mma16816(acc[f], A_h, Bfh[f][0], Bfh[f][1]);
                mma16816(acc[f], A_h, Bfl[f][0], Bfl[f][1]);
                mma16816(acc[f], A_l, Bfh[f][0], Bfh[f][1]);
            }
        }
        if (it + 2 < 32) { issue((it + 2) % 3, (it + 2) * 32); CP_COMMIT(); }
    }

    const int n_lo = n0 + warp * 16 + g;
#pragma unroll
    for (int f = 0; f < 8; f++) {
        int col = bd0 + f * 8 + tg * 2;
#pragma unroll
        for (int h = 0; h < 2; h++) {
            int n = n_lo + h * 8;
            *reinterpret_cast<float2*>(&g_s1[(size_t)n * (BB * DIN) + col]) =
                make_float2(acc[f][h * 2], acc[f][h * 2 + 1]);
        }
    }
}

// ---------------------------------------------------------------------------
// K6: out[b,n,o] = bias[n,o] + sum_{k,i} xg[k][n,b,i] w[n,k,i,o]
// 128 threads = 8 ki-splits x 16 o-quads; all 8 batches in registers.
// Each w LDS.128 feeds 32 FFMA. Cross-split reduce via smem.
// ---------------------------------------------------------------------------
__global__ __launch_bounds__(128) void out_kernel(float* __restrict__ out) {
    const int n = blockIdx.x, t = threadIdx.x;
    __shared__ float wS[KIO];            // 32 KB, layout [k][i][o] = [ki][o]
    __shared__ float xgS[2][BB][DIN];    // 4 KB
    __shared__ float bSh[DOUT];
    __shared__ float red[8][BB][68];     // 17.4 KB split partials
    const float* wp = g_w + (size_t)n * KIO;
#pragma unroll
    for (int l = 0; l < 16; l++) {
        int idx4 = t + l * 128;          // 2048 float4s
        *reinterpret_cast<float4*>(&wS[idx4 * 4]) =
            *reinterpret_cast<const float4*>(&wp[idx4 * 4]);
    }
#pragma unroll
    for (int l = 0; l < 2; l++) {
        int idx4 = t + l * 128;          // 256 float4s
        float* xgFlat = &xgS[0][0][0];
        const float* src = (idx4 < 128) ? (g_sxT + (size_t)n * (BB * DIN) + idx4 * 4)
                                        : (g_s1  + (size_t)n * (BB * DIN) + (idx4 - 128) * 4);
        *reinterpret_cast<float4*>(&xgFlat[idx4 * 4]) =
            *reinterpret_cast<const float4*>(src);
    }
    if (t < DOUT) bSh[t] = g_bias[n * DOUT + t];
    __syncthreads();

    const int sp = t >> 4;               // ki-split 0..7 (16 ki each)
    const int og = t & 15;               // o-quad
    const int o4 = og * 4;
    float acc[BB][4] = {};
#pragma unroll
    for (int ii = 0; ii < 16; ii++) {
        int ki = sp * 16 + ii;
        int k = ki >> 6, i = ki & 63;
        float4 wv = *reinterpret_cast<const float4*>(&wS[ki * 64 + o4]);
#pragma unroll
        for (int b = 0; b < BB; b++) {
            float xv = xgS[k][b][i];     // broadcast across the 16 og threads
            acc[b][0] += xv * wv.x;
            acc[b][1] += xv * wv.y;
            acc[b][2] += xv * wv.z;
            acc[b][3] += xv * wv.w;
        }
    }
#pragma unroll
    for (int b = 0; b < BB; b++)
        *reinterpret_cast<float4*>(&red[sp][b][o4]) =
            make_float4(acc[b][0], acc[b][1], acc[b][2], acc[b][3]);
    __syncthreads();

    {
        const int b = t >> 4, o4e = (t & 15) * 4;
        float4 r = make_float4(bSh[o4e], bSh[o4e + 1], bSh[o4e + 2], bSh[o4e + 3]);
#pragma unroll
        for (int s = 0; s < 8; s++) {
            float4 p = *reinterpret_cast<const float4*>(&red[s][b][o4e]);
            r.x += p.x; r.y += p.y; r.z += p.z; r.w += p.w;
        }
        *reinterpret_cast<float4*>(&out[((size_t)b * NN + n) * DOUT + o4e]) = r;
    }
}

// ---------------------------------------------------------------------------
extern "C" void kernel_launch(void* const* d_in, const int* in_sizes, int n_in,
                              void* d_out, int out_size) {
    const float* x    = (const float*)d_in[0];   // [8,1024,64]
    const float* E    = (const float*)d_in[1];   // [1024,16]
    const float* pa   = (const float*)d_in[2];   // [8,1024,16]
    const float* Wp   = (const float*)d_in[3];   // [16,2,64,64]
    const float* bp   = (const float*)d_in[4];   // [16,64]
    float* out = (float*)d_out;                  // [8,1024,64]

    sim_kernel<<<NN, 256>>>(E);
    weights_kernel<<<dim3(KIO / 256, NN / 128), 256>>>(E, Wp);
    bias_kernel<<<NN * DOUT / 256, 256>>>(E, bp);
    e_kernel<<<dim3(136, BB), 256>>>(pa);
    sinv_kernel<<<BB * NN / 256, 256>>>();
    xs_kernel<<<BB * NN * DIN / 1024, 256>>>(x);
    sx_mma_kernel<<<dim3(NN / 64, BB), 128>>>();
    s1_mma_kernel<<<dim3(NN / 64, BB * DIN / 64), 128>>>();
    out_kernel<<<NN, 128>>>(out);
}

// round 11
// speedup vs baseline: 2.4274x; 1.0919x over previous
#include <cuda_runtime.h>
#include <cuda_bf16.h>
#include <cstdint>

#define NN 1024
#define BB 8
#define DIN 64
#define DOUT 64
#define EMB 16
#define DPE 16
#define KIO 8192   // 2*64*64

// ---- device scratch (no allocations allowed) ----
__device__ __nv_bfloat16 g_e_hi[(size_t)BB * NN * NN];   // 16 MB
__device__ __nv_bfloat16 g_e_lo[(size_t)BB * NN * NN];   // 16 MB
__device__ __nv_bfloat16 g_sim_hi[NN * NN];              // 2 MB
__device__ __nv_bfloat16 g_sim_lo[NN * NN];              // 2 MB
__device__ __nv_bfloat16 g_xs_hi[BB * NN * DIN];         // 1 MB  (x*Sinv)
__device__ __nv_bfloat16 g_xs_lo[BB * NN * DIN];         // 1 MB
__device__ __nv_bfloat16 g_sxT_hi[NN * BB * DIN];        // 1 MB
__device__ __nv_bfloat16 g_sxT_lo[NN * BB * DIN];        // 1 MB
__device__ float g_w[NN * KIO];           // 32 MB  weights[n][k][i][o]
__device__ float g_bias[NN * DOUT];       // 256 KB
__device__ float g_part[BB * NN * 16];    // 512 KB row-sum partials
__device__ float g_sxT[NN * BB * DIN];    // 2 MB
__device__ float g_s1[NN * BB * DIN];     // 2 MB

// ---------- helpers ----------
static __device__ __forceinline__ unsigned int s2u(const void* p) {
    return (unsigned int)__cvta_generic_to_shared(p);
}
static __device__ __forceinline__ void ldsm_x4(unsigned r[4], unsigned int addr) {
    asm volatile("ldmatrix.sync.aligned.m8n8.x4.shared.b16 {%0,%1,%2,%3}, [%4];"
        : "=r"(r[0]), "=r"(r[1]), "=r"(r[2]), "=r"(r[3]) : "r"(addr));
}
static __device__ __forceinline__ void ldsm_x4_t(unsigned r[4], unsigned int addr) {
    asm volatile("ldmatrix.sync.aligned.m8n8.x4.trans.shared.b16 {%0,%1,%2,%3}, [%4];"
        : "=r"(r[0]), "=r"(r[1]), "=r"(r[2]), "=r"(r[3]) : "r"(addr));
}
static __device__ __forceinline__ void mma16816(float c[4], const unsigned a[4], const unsigned b0, const unsigned b1) {
    asm volatile("mma.sync.aligned.m16n8k16.row.col.f32.bf16.bf16.f32 "
        "{%0,%1,%2,%3}, {%4,%5,%6,%7}, {%8,%9}, {%0,%1,%2,%3};"
        : "+f"(c[0]), "+f"(c[1]), "+f"(c[2]), "+f"(c[3])
        : "r"(a[0]), "r"(a[1]), "r"(a[2]), "r"(a[3]), "r"(b0), "r"(b1));
}
static __device__ __forceinline__ void cpa16(void* dst, const void* src) {
    unsigned int d = s2u(dst);
    asm volatile("cp.async.ca.shared.global [%0], [%1], 16;" :: "r"(d), "l"(src));
}
#define CP_COMMIT() asm volatile("cp.async.commit_group;" ::: "memory")
#define CP_WAIT1()  asm volatile("cp.async.wait_group 1;" ::: "memory")
#define CP_WAIT0()  asm volatile("cp.async.wait_group 0;" ::: "memory")

static __device__ __forceinline__ void split_store(float v, __nv_bfloat16* hi, __nv_bfloat16* lo, size_t off) {
    __nv_bfloat16 h = __float2bfloat16(v);
    hi[off] = h;
    lo[off] = __float2bfloat16(v - __bfloat162float(h));
}
static __device__ __forceinline__ void split_pair(float v0, float v1,
                                                  __nv_bfloat162& hv, __nv_bfloat162& lv) {
    hv = __floats2bfloat162_rn(v0, v1);
    float2 hf = __bfloat1622float2(hv);
    lv = __floats2bfloat162_rn(v0 - hf.x, v1 - hf.y);
}

// e^{-d} for d >= 0, FFMA-only (no MUFU). Max rel err ~2e-8.
static __device__ __forceinline__ float fexp_neg(float d) {
    float z = d * -1.442695040888963f;       // log2(e)
    z = fmaxf(z, -126.0f);                   // underflow clamp (exact 0-ish anyway)
    float n = rintf(z);
    float f = z - n;                         // f in [-0.5, 0.5]
    float p = 1.54035304e-4f;                // 2^f Taylor (ln2^k/k!)
    p = fmaf(p, f, 1.33335581e-3f);
    p = fmaf(p, f, 9.61812911e-3f);
    p = fmaf(p, f, 5.55041087e-2f);
    p = fmaf(p, f, 2.40226507e-1f);
    p = fmaf(p, f, 6.93147181e-1f);
    p = fmaf(p, f, 1.0f);
    int e = (int)n;
    return p * __int_as_float((127 + e) << 23);
}

// ---------------------------------------------------------------------------
// K0: sim = softmax(relu(E E^T), axis=1) -> bf16 hi/lo.  one block per row
// ---------------------------------------------------------------------------
__global__ __launch_bounds__(256) void sim_kernel(const float* __restrict__ E) {
    const int i = blockIdx.x;
    const int t = threadIdx.x;
    __shared__ float Ei[EMB];
    __shared__ float red[256];
    if (t < EMB) Ei[t] = E[i * EMB + t];
    __syncthreads();

    float v[4];
    float mx = -1e30f;
#pragma unroll
    for (int r = 0; r < 4; r++) {
        int j = t + r * 256;
        const float4* Ej = reinterpret_cast<const float4*>(E + j * EMB);
        float acc = 0.f;
#pragma unroll
        for (int q = 0; q < 4; q++) {
            float4 e4 = Ej[q];
            acc += Ei[q * 4 + 0] * e4.x + Ei[q * 4 + 1] * e4.y
                 + Ei[q * 4 + 2] * e4.z + Ei[q * 4 + 3] * e4.w;
        }
        acc = fmaxf(acc, 0.f);
        v[r] = acc;
        mx = fmaxf(mx, acc);
    }
    red[t] = mx; __syncthreads();
    for (int s = 128; s > 0; s >>= 1) { if (t < s) red[t] = fmaxf(red[t], red[t + s]); __syncthreads(); }
    mx = red[0]; __syncthreads();

    float sum = 0.f;
#pragma unroll
    for (int r = 0; r < 4; r++) { v[r] = fexp_neg(mx - v[r]); sum += v[r]; }
    red[t] = sum; __syncthreads();
    for (int s = 128; s > 0; s >>= 1) { if (t < s) red[t] += red[t + s]; __syncthreads(); }
    float inv = 1.0f / red[0];
#pragma unroll
    for (int r = 0; r < 4; r++)
        split_store(v[r] * inv, g_sim_hi, g_sim_lo, (size_t)i * NN + t + r * 256);
}

// ---------------------------------------------------------------------------
// K1: weights[n, kio] = sum_d E[n,d] * Wp[d, kio]
// ---------------------------------------------------------------------------
__global__ __launch_bounds__(256) void weights_kernel(const float* __restrict__ E,
                                                      const float* __restrict__ Wp) {
    const int t = threadIdx.x;
    const int kio = blockIdx.x * 256 + t;
    const int n0 = blockIdx.y * 128;

    float w[EMB];
#pragma unroll
    for (int d = 0; d < EMB; d++) w[d] = Wp[d * KIO + kio];   // coalesced

    __shared__ float Es[128][20];
#pragma unroll
    for (int l = 0; l < 2; l++) {
        int idx4 = t + l * 256;
        int r = idx4 >> 2, q4 = (idx4 & 3) * 4;
        *reinterpret_cast<float4*>(&Es[r][q4]) =
            *reinterpret_cast<const float4*>(&E[(n0 + r) * EMB + q4]);
    }
    __syncthreads();

    float* outp = g_w + (size_t)n0 * KIO + kio;
#pragma unroll 4
    for (int nn = 0; nn < 128; nn++) {
        float4 e0 = *reinterpret_cast<const float4*>(&Es[nn][0]);
        float4 e1 = *reinterpret_cast<const float4*>(&Es[nn][4]);
        float4 e2 = *reinterpret_cast<const float4*>(&Es[nn][8]);
        float4 e3 = *reinterpret_cast<const float4*>(&Es[nn][12]);
        float a0 = e0.x * w[0] + e0.y * w[1] + e0.z * w[2] + e0.w * w[3]
                 + e1.x * w[4] + e1.y * w[5] + e1.z * w[6] + e1.w * w[7];
        float a1 = e2.x * w[8] + e2.y * w[9] + e2.z * w[10] + e2.w * w[11]
                 + e3.x * w[12] + e3.y * w[13] + e3.z * w[14] + e3.w * w[15];
        outp[(size_t)nn * KIO] = a0 + a1;
    }
}

// K1b: bias[n,o] = sum_d E[n,d] * bp[d,o]
__global__ __launch_bounds__(256) void bias_kernel(const float* __restrict__ E,
                                                   const float* __restrict__ bp) {
    int idx = blockIdx.x * 256 + threadIdx.x;       // 65536
    int n = idx >> 6, o = idx & 63;
    float acc = 0.f;
#pragma unroll
    for (int d = 0; d < EMB; d++) acc += E[n * EMB + d] * bp[d * DOUT + o];
    g_bias[idx] = acc;
}

// ---------------------------------------------------------------------------
// K2: e[b,i,j] = exp(-sum_d |pa[b,i,d]-pa[b,j,d]|) -> bf16 hi/lo, packed stores.
// Upper-tri tiles only; transposed tile + row/col partials via smem.
// FFMA-only exp (kernel was MUFU-bound).
// ---------------------------------------------------------------------------
__global__ __launch_bounds__(256) void e_kernel(const float* __restrict__ pa) {
    const int b = blockIdx.y;
    int rem = blockIdx.x, ti = 0;
    while (rem >= 16 - ti) { rem -= 16 - ti; ti++; }
    const int tjt = ti + rem;
    const int i0 = ti * 64, j0 = tjt * 64;
    const int t = threadIdx.x;
    const int cp = t & 31, rg = t >> 5;
    const int c0 = cp * 2;

    __shared__ float paI[64][20];
    __shared__ float paJ[64][20];
    __shared__ float vS[64][65];
    __shared__ float cpS[8][64];
    __shared__ float rpS[4][64];

    const float* paB = pa + (size_t)b * NN * DPE;
    {
        int r = t >> 2, q4 = (t & 3) * 4;
        *reinterpret_cast<float4*>(&paI[r][q4]) =
            *reinterpret_cast<const float4*>(&paB[(i0 + r) * DPE + q4]);
        *reinterpret_cast<float4*>(&paJ[r][q4]) =
            *reinterpret_cast<const float4*>(&paB[(j0 + r) * DPE + q4]);
    }
    __syncthreads();

    float pj0[16], pj1[16];
#pragma unroll
    for (int q = 0; q < 4; q++) {
        float4 u = *reinterpret_cast<const float4*>(&paJ[c0][q * 4]);
        pj0[q * 4 + 0] = u.x; pj0[q * 4 + 1] = u.y; pj0[q * 4 + 2] = u.z; pj0[q * 4 + 3] = u.w;
        float4 w = *reinterpret_cast<const float4*>(&paJ[c0 + 1][q * 4]);
        pj1[q * 4 + 0] = w.x; pj1[q * 4 + 1] = w.y; pj1[q * 4 + 2] = w.z; pj1[q * 4 + 3] = w.w;
    }

    const unsigned baseD = (unsigned)((b * NN + i0) * NN + j0);
    float cps0 = 0.f, cps1 = 0.f;
#pragma unroll
    for (int s = 0; s < 8; s++) {
        int i = rg * 8 + s;
        float4 p0 = *reinterpret_cast<const float4*>(&paI[i][0]);
        float4 p1 = *reinterpret_cast<const float4*>(&paI[i][4]);
        float4 p2 = *reinterpret_cast<const float4*>(&paI[i][8]);
        float4 p3 = *reinterpret_cast<const float4*>(&paI[i][12]);
        float d0 = (((fabsf(p0.x - pj0[0])  + fabsf(p0.y - pj0[1]))
                  +  (fabsf(p0.z - pj0[2])  + fabsf(p0.w - pj0[3])))
                 +  ((fabsf(p1.x - pj0[4])  + fabsf(p1.y - pj0[5]))
                  +  (fabsf(p1.z - pj0[6])  + fabsf(p1.w - pj0[7]))))
                 + (((fabsf(p2.x - pj0[8])  + fabsf(p2.y - pj0[9]))
                  +  (fabsf(p2.z - pj0[10]) + fabsf(p2.w - pj0[11])))
                 +  ((fabsf(p3.x - pj0[12]) + fabsf(p3.y - pj0[13]))
                  +  (fabsf(p3.z - pj0[14]) + fabsf(p3.w - pj0[15]))));
        float d1 = (((fabsf(p0.x - pj1[0])  + fabsf(p0.y - pj1[1]))
                  +  (fabsf(p0.z - pj1[2])  + fabsf(p0.w - pj1[3])))
                 +  ((fabsf(p1.x - pj1[4])  + fabsf(p1.y - pj1[5]))
                  +  (fabsf(p1.z - pj1[6])  + fabsf(p1.w - pj1[7]))))
                 + (((fabsf(p2.x - pj1[8])  + fabsf(p2.y - pj1[9]))
                  +  (fabsf(p2.z - pj1[10]) + fabsf(p2.w - pj1[11])))
                 +  ((fabsf(p3.x - pj1[12]) + fabsf(p3.y - pj1[13]))
                  +  (fabsf(p3.z - pj1[14]) + fabsf(p3.w - pj1[15]))));
        float v0 = fexp_neg(d0), v1 = fexp_neg(d1);
        vS[i][c0] = v0; vS[i][c0 + 1] = v1;
        cps0 += v0; cps1 += v1;
        __nv_bfloat162 hv, lv; split_pair(v0, v1, hv, lv);
        unsigned off = baseD + (unsigned)i * NN + c0;
        *reinterpret_cast<__nv_bfloat162*>(g_e_hi + off) = hv;
        *reinterpret_cast<__nv_bfloat162*>(g_e_lo + off) = lv;
    }
    cpS[rg][c0] = cps0; cpS[rg][c0 + 1] = cps1;
    __syncthreads();

    {
        int r = t & 63, qq = t >> 6;
        float s = 0.f;
#pragma unroll
        for (int c = 0; c < 16; c++) s += vS[r][qq * 16 + c];
        rpS[qq][r] = s;
    }
    __syncthreads();

    if (t < 64) {
        float rowP = rpS[0][t] + rpS[1][t] + rpS[2][t] + rpS[3][t];
        g_part[((size_t)b * NN + i0 + t) * 16 + tjt] = rowP;
    } else if (t < 128 && ti != tjt) {
        int c = t - 64;
        float colP = 0.f;
#pragma unroll
        for (int q = 0; q < 8; q++) colP += cpS[q][c];
        g_part[((size_t)b * NN + j0 + c) * 16 + ti] = colP;
    }

    if (ti != tjt) {
        const unsigned baseT = (unsigned)((b * NN + j0) * NN + i0);
#pragma unroll
        for (int s = 0; s < 8; s++) {
            int r2 = rg * 8 + s;
            float v0 = vS[c0][r2], v1 = vS[c0 + 1][r2];
            __nv_bfloat162 hv, lv; split_pair(v0, v1, hv, lv);
            unsigned off = baseT + (unsigned)r2 * NN + c0;
            *reinterpret_cast<__nv_bfloat162*>(g_e_hi + off) = hv;
            *reinterpret_cast<__nv_bfloat162*>(g_e_lo + off) = lv;
        }
    }
}

// ---------------------------------------------------------------------------
// K3: merged Sinv + xs:  xs[row,d] = x[row,d] / sum_k part[row][k]
// block = 16 rows; grid 512.
// ---------------------------------------------------------------------------
__global__ __launch_bounds__(256) void sinv_xs_kernel(const float* __restrict__ x) {
    const int row0 = blockIdx.x * 16;
    const int t = threadIdx.x;
    __shared__ float sInv[16];
    if (t < 16) {
        const float* p = g_part + (size_t)(row0 + t) * 16;
        float s = 0.f;
#pragma unroll
        for (int k = 0; k < 16; k++) s += p[k];
        sInv[t] = 1.0f / s;
    }
    __syncthreads();
    const int rloc = t >> 4, d4 = (t & 15) * 4;
    const size_t row = row0 + rloc;
    float4 v = *reinterpret_cast<const float4*>(&x[row * DIN + d4]);
    float s = sInv[rloc];
    v.x *= s; v.y *= s; v.z *= s; v.w *= s;
    __nv_bfloat162 h0, l0, h1, l1;
    split_pair(v.x, v.y, h0, l0);
    split_pair(v.z, v.w, h1, l1);
    *reinterpret_cast<__nv_bfloat162*>(&g_xs_hi[row * DIN + d4]) = h0;
    *reinterpret_cast<__nv_bfloat162*>(&g_xs_hi[row * DIN + d4 + 2]) = h1;
    *reinterpret_cast<__nv_bfloat162*>(&g_xs_lo[row * DIN + d4]) = l0;
    *reinterpret_cast<__nv_bfloat162*>(&g_xs_lo[row * DIN + d4 + 2]) = l1;
}

// ---------------------------------------------------------------------------
// K4: sxT[m][b][d] = sum_c e[b,m,c] * xs[b,c,d]  via bf16 mma (3-pass split)
// 256 threads, split-K across 2 warpgroups (BK=64), 2-stage cp.async,
// smem reduce of the two K-half accumulators.  grid (16 m-tiles, 8 b)
// ---------------------------------------------------------------------------
__global__ __launch_bounds__(256) void sx_mma_kernel() {
    const int b = blockIdx.y, m0 = blockIdx.x * 64;
    const int t = threadIdx.x;
    const int warp = t >> 5, lane = t & 31;
    const int wg = warp >> 2, w4 = warp & 3;
    const int g = lane >> 2, tg = lane & 3;

    __shared__ __nv_bfloat16 Ah[2][64][72], Al[2][64][72];
    __shared__ __nv_bfloat16 Bh[2][64][72], Bl[2][64][72];
    __shared__ float redS[4][16][64];

    const __nv_bfloat16* eHi = g_e_hi + ((size_t)b * NN + m0) * NN;
    const __nv_bfloat16* eLo = g_e_lo + ((size_t)b * NN + m0) * NN;
    const __nv_bfloat16* xHi = g_xs_hi + (size_t)b * NN * DIN;
    const __nv_bfloat16* xLo = g_xs_lo + (size_t)b * NN * DIN;

    float acc[8][4] = {};
    const int lrow = lane & 15;
    const int lcol = (lane & 16) >> 1;

    auto issue = [&](int st, int c0) {
#pragma unroll
        for (int l = 0; l < 2; l++) {
            int idx = t + l * 256;                   // 512: 64 rows x 8 quads
            int r = idx >> 3, q = (idx & 7) * 8;
            cpa16(&Ah[st][r][q], &eHi[(size_t)r * NN + c0 + q]);
            cpa16(&Al[st][r][q], &eLo[(size_t)r * NN + c0 + q]);
        }
#pragma unroll
        for (int l = 0; l < 2; l++) {
            int idx = t + l * 256;                   // 512: 64 k-rows x 8 quads
            int r = idx >> 3, q = (idx & 7) * 8;
            cpa16(&Bh[st][r][q], &xHi[(size_t)(c0 + r) * DIN + q]);
            cpa16(&Bl[st][r][q], &xLo[(size_t)(c0 + r) * DIN + q]);
        }
    };

    issue(0, 0); CP_COMMIT();
    for (int it = 0; it < 16; it++) {
        int cur = it & 1;
        if (it < 15) { issue(cur ^ 1, (it + 1) * 64); CP_COMMIT(); CP_WAIT1(); }
        else CP_WAIT0();
        __syncthreads();

#pragma unroll
        for (int k16 = 0; k16 < 2; k16++) {
            int kk = wg * 2 + k16;                   // this warpgroup's K-quarter
            unsigned A_h[4], A_l[4];
            ldsm_x4(A_h, s2u(&Ah[cur][w4 * 16 + lrow][kk * 16 + lcol]));
            ldsm_x4(A_l, s2u(&Al[cur][w4 * 16 + lrow][kk * 16 + lcol]));
            unsigned Bfh[8][2], Bfl[8][2];
#pragma unroll
            for (int nb = 0; nb < 4; nb++) {
                unsigned tmp[4];
                ldsm_x4_t(tmp, s2u(&Bh[cur][kk * 16 + lrow][nb * 16 + lcol]));
                Bfh[nb * 2][0] = tmp[0]; Bfh[nb * 2][1] = tmp[1];
                Bfh[nb * 2 + 1][0] = tmp[2]; Bfh[nb * 2 + 1][1] = tmp[3];
                ldsm_x4_t(tmp, s2u(&Bl[cur][kk * 16 + lrow][nb * 16 + lcol]));
                Bfl[nb * 2][0] = tmp[0]; Bfl[nb * 2][1] = tmp[1];
                Bfl[nb * 2 + 1][0] = tmp[2]; Bfl[nb * 2 + 1][1] = tmp[3];
            }
#pragma unroll
            for (int f = 0; f < 8; f++) {
                mma16816(acc[f], A_h, Bfh[f][0], Bfh[f][1]);
                mma16816(acc[f], A_h, Bfl[f][0], Bfl[f][1]);
                mma16816(acc[f], A_l, Bfh[f][0], Bfh[f][1]);
            }
        }
        __syncthreads();
    }

    // cross-warpgroup K reduce, then epilogue by wg0
    if (wg == 1) {
#pragma unroll
        for (int f = 0; f < 8; f++)
#pragma unroll
            for (int h = 0; h < 2; h++)
                *reinterpret_cast<float2*>(&redS[w4][g + h * 8][f * 8 + tg * 2]) =
                    make_float2(acc[f][h * 2], acc[f][h * 2 + 1]);
    }
    __syncthreads();
    if (wg == 0) {
        const int m_lo = m0 + w4 * 16 + g;
#pragma unroll
        for (int f = 0; f < 8; f++) {
            int col = f * 8 + tg * 2;
#pragma unroll
            for (int h = 0; h < 2; h++) {
                float2 r = *reinterpret_cast<const float2*>(&redS[w4][g + h * 8][col]);
                float vx = acc[f][h * 2] + r.x, vy = acc[f][h * 2 + 1] + r.y;
                int m = m_lo + h * 8;
                size_t o = ((size_t)m * BB + b) * DIN + col;
                *reinterpret_cast<float2*>(&g_sxT[o]) = make_float2(vx, vy);
                __nv_bfloat162 hv, lv; split_pair(vx, vy, hv, lv);
                *reinterpret_cast<__nv_bfloat162*>(&g_sxT_hi[o]) = hv;
                *reinterpret_cast<__nv_bfloat162*>(&g_sxT_lo[o]) = lv;
            }
        }
    }
}

// ---------------------------------------------------------------------------
// K5: s1[n][bd] = sum_m sim[n,m] * sxT[m][bd]  — same split-K scheme.
// grid (16 n-tiles, 8 bd-tiles)
// ---------------------------------------------------------------------------
__global__ __launch_bounds__(256) void s1_mma_kernel() {
    const int n0 = blockIdx.x * 64, bd0 = blockIdx.y * 64;
    const int t = threadIdx.x;
    const int warp = t >> 5, lane = t & 31;
    const int wg = warp >> 2, w4 = warp & 3;
    const int g = lane >> 2, tg = lane & 3;

    __shared__ __nv_bfloat16 Ah[2][64][72], Al[2][64][72];
    __shared__ __nv_bfloat16 Bh[2][64][72], Bl[2][64][72];
    __shared__ float redS[4][16][64];

    const __nv_bfloat16* aHi = g_sim_hi + (size_t)n0 * NN;
    const __nv_bfloat16* aLo = g_sim_lo + (size_t)n0 * NN;

    float acc[8][4] = {};
    const int lrow = lane & 15;
    const int lcol = (lane & 16) >> 1;

    auto issue = [&](int st, int c0) {
#pragma unroll
        for (int l = 0; l < 2; l++) {
            int idx = t + l * 256;
            int r = idx >> 3, q = (idx & 7) * 8;
            cpa16(&Ah[st][r][q], &aHi[(size_t)r * NN + c0 + q]);
            cpa16(&Al[st][r][q], &aLo[(size_t)r * NN + c0 + q]);
        }
#pragma unroll
        for (int l = 0; l < 2; l++) {
            int idx = t + l * 256;
            int r = idx >> 3, q = (idx & 7) * 8;
            cpa16(&Bh[st][r][q], &g_sxT_hi[(size_t)(c0 + r) * (BB * DIN) + bd0 + q]);
            cpa16(&Bl[st][r][q], &g_sxT_lo[(size_t)(c0 + r) * (BB * DIN) + bd0 + q]);
        }
    };

    issue(0, 0); CP_COMMIT();
    for (int it = 0; it < 16; it++) {
        int cur = it & 1;
        if (it < 15) { issue(cur ^ 1, (it + 1) * 64); CP_COMMIT(); CP_WAIT1(); }
        else CP_WAIT0();
        __syncthreads();

#pragma unroll
        for (int k16 = 0; k16 < 2; k16++) {
            int kk = wg * 2 + k16;
            unsigned A_h[4], A_l[4];
            ldsm_x4(A_h, s2u(&Ah[cur][w4 * 16 + lrow][kk * 16 + lcol]));
            ldsm_x4(A_l, s2u(&Al[cur][w4 * 16 + lrow][kk * 16 + lcol]));
            unsigned Bfh[8][2], Bfl[8][2];
#pragma unroll
            for (int nb = 0; nb < 4; nb++) {
                unsigned tmp[4];
                ldsm_x4_t(tmp, s2u(&Bh[cur][kk * 16 + lrow][nb * 16 + lcol]));
                Bfh[nb * 2][0] = tmp[0]; Bfh[nb * 2][1] = tmp[1];
                Bfh[nb * 2 + 1][0] = tmp[2]; Bfh[nb * 2 + 1][1] = tmp[3];
                ldsm_x4_t(tmp, s2u(&Bl[cur][kk * 16 + lrow][nb * 16 + lcol]));
                Bfl[nb * 2][0] = tmp[0]; Bfl[nb * 2][1] = tmp[1];
                Bfl[nb * 2 + 1][0] = tmp[2]; Bfl[nb * 2 + 1][1] = tmp[3];
            }
#pragma unroll
            for (int f = 0; f < 8; f++) {
                mma16816(acc[f], A_h, Bfh[f][0], Bfh[f][1]);
                mma16816(acc[f], A_h, Bfl[f][0], Bfl[f][1]);
                mma16816(acc[f], A_l, Bfh[f][0], Bfh[f][1]);
            }
        }
        __syncthreads();
    }

    if (wg == 1) {
#pragma unroll
        for (int f = 0; f < 8; f++)
#pragma unroll
            for (int h = 0; h < 2; h++)
                *reinterpret_cast<float2*>(&redS[w4][g + h * 8][f * 8 + tg * 2]) =
                    make_float2(acc[f][h * 2], acc[f][h * 2 + 1]);
    }
    __syncthreads();
    if (wg == 0) {
        const int n_lo = n0 + w4 * 16 + g;
#pragma unroll
        for (int f = 0; f < 8; f++) {
            int col = f * 8 + tg * 2;
#pragma unroll
            for (int h = 0; h < 2; h++) {
                float2 r = *reinterpret_cast<const float2*>(&redS[w4][g + h * 8][col]);
                int n = n_lo + h * 8;
                *reinterpret_cast<float2*>(&g_s1[(size_t)n * (BB * DIN) + bd0 + col]) =
                    make_float2(acc[f][h * 2] + r.x, acc[f][h * 2 + 1] + r.y);
            }
        }
    }
}

// ---------------------------------------------------------------------------
// K6: out[b,n,o] = bias[n,o] + sum_{k,i} xg[k][n,b,i] w[n,k,i,o]
// ---------------------------------------------------------------------------
__global__ __launch_bounds__(128) void out_kernel(float* __restrict__ out) {
    const int n = blockIdx.x, t = threadIdx.x;
    __shared__ float wS[KIO];
    __shared__ float xgS[2][BB][DIN];
    __shared__ float bSh[DOUT];
    __shared__ float red[8][BB][68];
    const float* wp = g_w + (size_t)n * KIO;
#pragma unroll
    for (int l = 0; l < 16; l++) {
        int idx4 = t + l * 128;
        *reinterpret_cast<float4*>(&wS[idx4 * 4]) =
            *reinterpret_cast<const float4*>(&wp[idx4 * 4]);
    }
#pragma unroll
    for (int l = 0; l < 2; l++) {
        int idx4 = t + l * 128;
        float* xgFlat = &xgS[0][0][0];
        const float* src = (idx4 < 128) ? (g_sxT + (size_t)n * (BB * DIN) + idx4 * 4)
                                        : (g_s1  + (size_t)n * (BB * DIN) + (idx4 - 128) * 4);
        *reinterpret_cast<float4*>(&xgFlat[idx4 * 4]) =
            *reinterpret_cast<const float4*>(src);
    }
    if (t < DOUT) bSh[t] = g_bias[n * DOUT + t];
    __syncthreads();

    const int sp = t >> 4;
    const int og = t & 15;
    const int o4 = og * 4;
    float acc[BB][4] = {};
#pragma unroll
    for (int ii = 0; ii < 16; ii++) {
        int ki = sp * 16 + ii;
        int k = ki >> 6, i = ki & 63;
        float4 wv = *reinterpret_cast<const float4*>(&wS[ki * 64 + o4]);
#pragma unroll
        for (int b = 0; b < BB; b++) {
            float xv = xgS[k][b][i];
            acc[b][0] += xv * wv.x;
            acc[b][1] += xv * wv.y;
            acc[b][2] += xv * wv.z;
            acc[b][3] += xv * wv.w;
        }
    }
#pragma unroll
    for (int b = 0; b < BB; b++)
        *reinterpret_cast<float4*>(&red[sp][b][o4]) =
            make_float4(acc[b][0], acc[b][1], acc[b][2], acc[b][3]);
    __syncthreads();

    {
        const int b = t >> 4, o4e = (t & 15) * 4;
        float4 r = make_float4(bSh[o4e], bSh[o4e + 1], bSh[o4e + 2], bSh[o4e + 3]);
#pragma unroll
        for (int s = 0; s < 8; s++) {
            float4 p = *reinterpret_cast<const float4*>(&red[s][b][o4e]);
            r.x += p.x; r.y += p.y; r.z += p.z; r.w += p.w;
        }
        *reinterpret_cast<float4*>(&out[((size_t)b * NN + n) * DOUT + o4e]) = r;
    }
}

// ---------------------------------------------------------------------------
extern "C" void kernel_launch(void* const* d_in, const int* in_sizes, int n_in,
                              void* d_out, int out_size) {
    const float* x    = (const float*)d_in[0];   // [8,1024,64]
    const float* E    = (const float*)d_in[1];   // [1024,16]
    const float* pa   = (const float*)d_in[2];   // [8,1024,16]
    const float* Wp   = (const float*)d_in[3];   // [16,2,64,64]
    const float* bp   = (const float*)d_in[4];   // [16,64]
    float* out = (float*)d_out;                  // [8,1024,64]

    sim_kernel<<<NN, 256>>>(E);
    weights_kernel<<<dim3(KIO / 256, NN / 128), 256>>>(E, Wp);
    bias_kernel<<<NN * DOUT / 256, 256>>>(E, bp);
    e_kernel<<<dim3(136, BB), 256>>>(pa);
    sinv_xs_kernel<<<BB * NN / 16, 256>>>(x);
    sx_mma_kernel<<<dim3(NN / 64, BB), 256>>>();
    s1_mma_kernel<<<dim3(NN / 64, BB * DIN / 64), 256>>>();
    out_kernel<<<NN, 128>>>(out);
}

// round 12
// speedup vs baseline: 2.6826x; 1.1051x over previous
#include <cuda_runtime.h>
#include <cuda_bf16.h>
#include <cstdint>

#define NN 1024
#define BB 8
#define DIN 64
#define DOUT 64
#define EMB 16
#define DPE 16
#define KIO 8192   // 2*64*64

// ---- device scratch (no allocations allowed) ----
// e stored CANONICALLY only: tile (ti,tj) with ti<=tj holds e values for that
// block; lower-triangle reads go through the symmetric transposed path.
__device__ __nv_bfloat16 g_e_hi[(size_t)BB * NN * NN];   // 16 MB
__device__ __nv_bfloat16 g_e_lo[(size_t)BB * NN * NN];   // 16 MB
__device__ __nv_bfloat16 g_sim_hi[NN * NN];              // 2 MB
__device__ __nv_bfloat16 g_sim_lo[NN * NN];              // 2 MB
__device__ __nv_bfloat16 g_xs_hi[BB * NN * DIN];         // 1 MB  (x*Sinv)
__device__ __nv_bfloat16 g_xs_lo[BB * NN * DIN];         // 1 MB
__device__ __nv_bfloat16 g_sxT_hi[NN * BB * DIN];        // 1 MB
__device__ __nv_bfloat16 g_sxT_lo[NN * BB * DIN];        // 1 MB
__device__ float g_w[NN * KIO];           // 32 MB  weights[n][k][i][o]
__device__ float g_bias[NN * DOUT];       // 256 KB
__device__ float g_part[BB * NN * 16];    // 512 KB row-sum partials
__device__ float g_sxT[NN * BB * DIN];    // 2 MB
__device__ float g_s1[NN * BB * DIN];     // 2 MB

// ---------- helpers ----------
static __device__ __forceinline__ unsigned int s2u(const void* p) {
    return (unsigned int)__cvta_generic_to_shared(p);
}
static __device__ __forceinline__ void ldsm_x4(unsigned r[4], unsigned int addr) {
    asm volatile("ldmatrix.sync.aligned.m8n8.x4.shared.b16 {%0,%1,%2,%3}, [%4];"
        : "=r"(r[0]), "=r"(r[1]), "=r"(r[2]), "=r"(r[3]) : "r"(addr));
}
static __device__ __forceinline__ void ldsm_x4_t(unsigned r[4], unsigned int addr) {
    asm volatile("ldmatrix.sync.aligned.m8n8.x4.trans.shared.b16 {%0,%1,%2,%3}, [%4];"
        : "=r"(r[0]), "=r"(r[1]), "=r"(r[2]), "=r"(r[3]) : "r"(addr));
}
static __device__ __forceinline__ void mma16816(float c[4], const unsigned a[4], const unsigned b0, const unsigned b1) {
    asm volatile("mma.sync.aligned.m16n8k16.row.col.f32.bf16.bf16.f32 "
        "{%0,%1,%2,%3}, {%4,%5,%6,%7}, {%8,%9}, {%0,%1,%2,%3};"
        : "+f"(c[0]), "+f"(c[1]), "+f"(c[2]), "+f"(c[3])
        : "r"(a[0]), "r"(a[1]), "r"(a[2]), "r"(a[3]), "r"(b0), "r"(b1));
}
static __device__ __forceinline__ void cpa16(void* dst, const void* src) {
    unsigned int d = s2u(dst);
    asm volatile("cp.async.ca.shared.global [%0], [%1], 16;" :: "r"(d), "l"(src));
}
#define CP_COMMIT() asm volatile("cp.async.commit_group;" ::: "memory")
#define CP_WAIT1()  asm volatile("cp.async.wait_group 1;" ::: "memory")
#define CP_WAIT0()  asm volatile("cp.async.wait_group 0;" ::: "memory")

static __device__ __forceinline__ void split_store(float v, __nv_bfloat16* hi, __nv_bfloat16* lo, size_t off) {
    __nv_bfloat16 h = __float2bfloat16(v);
    hi[off] = h;
    lo[off] = __float2bfloat16(v - __bfloat162float(h));
}
static __device__ __forceinline__ void split_pair(float v0, float v1,
                                                  __nv_bfloat162& hv, __nv_bfloat162& lv) {
    hv = __floats2bfloat162_rn(v0, v1);
    float2 hf = __bfloat1622float2(hv);
    lv = __floats2bfloat162_rn(v0 - hf.x, v1 - hf.y);
}

// e^{-d} for d >= 0, FFMA-only (no MUFU). Max rel err ~2e-8.
static __device__ __forceinline__ float fexp_neg(float d) {
    float z = d * -1.442695040888963f;       // log2(e)
    z = fmaxf(z, -126.0f);
    float n = rintf(z);
    float f = z - n;
    float p = 1.54035304e-4f;
    p = fmaf(p, f, 1.33335581e-3f);
    p = fmaf(p, f, 9.61812911e-3f);
    p = fmaf(p, f, 5.55041087e-2f);
    p = fmaf(p, f, 2.40226507e-1f);
    p = fmaf(p, f, 6.93147181e-1f);
    p = fmaf(p, f, 1.0f);
    int e = (int)n;
    return p * __int_as_float((127 + e) << 23);
}

// ---------------------------------------------------------------------------
// K0: sim = softmax(relu(E E^T), axis=1) -> bf16 hi/lo.  one block per row
// ---------------------------------------------------------------------------
__global__ __launch_bounds__(256) void sim_kernel(const float* __restrict__ E) {
    const int i = blockIdx.x;
    const int t = threadIdx.x;
    __shared__ float Ei[EMB];
    __shared__ float red[256];
    if (t < EMB) Ei[t] = E[i * EMB + t];
    __syncthreads();

    float v[4];
    float mx = -1e30f;
#pragma unroll
    for (int r = 0; r < 4; r++) {
        int j = t + r * 256;
        const float4* Ej = reinterpret_cast<const float4*>(E + j * EMB);
        float acc = 0.f;
#pragma unroll
        for (int q = 0; q < 4; q++) {
            float4 e4 = Ej[q];
            acc += Ei[q * 4 + 0] * e4.x + Ei[q * 4 + 1] * e4.y
                 + Ei[q * 4 + 2] * e4.z + Ei[q * 4 + 3] * e4.w;
        }
        acc = fmaxf(acc, 0.f);
        v[r] = acc;
        mx = fmaxf(mx, acc);
    }
    red[t] = mx; __syncthreads();
    for (int s = 128; s > 0; s >>= 1) { if (t < s) red[t] = fmaxf(red[t], red[t + s]); __syncthreads(); }
    mx = red[0]; __syncthreads();

    float sum = 0.f;
#pragma unroll
    for (int r = 0; r < 4; r++) { v[r] = fexp_neg(mx - v[r]); sum += v[r]; }
    red[t] = sum; __syncthreads();
    for (int s = 128; s > 0; s >>= 1) { if (t < s) red[t] += red[t + s]; __syncthreads(); }
    float inv = 1.0f / red[0];
#pragma unroll
    for (int r = 0; r < 4; r++)
        split_store(v[r] * inv, g_sim_hi, g_sim_lo, (size_t)i * NN + t + r * 256);
}

// ---------------------------------------------------------------------------
// K1: weights[n, kio] = sum_d E[n,d] * Wp[d, kio]  via bf16 mma (3-pass split).
// One K=16 mma step. Block: 64 n-rows x 256 kio-cols; 8 warps, each 32 cols.
// grid (KIO/256 = 32, NN/64 = 16)
// ---------------------------------------------------------------------------
__global__ __launch_bounds__(256) void weights_mma_kernel(const float* __restrict__ E,
                                                          const float* __restrict__ Wp) {
    const int kio0 = blockIdx.x * 256;
    const int n0 = blockIdx.y * 64;
    const int t = threadIdx.x;
    const int warp = t >> 5, lane = t & 31;
    const int g = lane >> 2, tg = lane & 3;
    const int lrow = lane & 15;
    const int lcol = (lane & 16) >> 1;

    __shared__ __nv_bfloat16 Ah[64][24], Al[64][24];     // E tile [n][d]
    __shared__ __nv_bfloat16 Bh[16][264], Bl[16][264];   // Wp tile [d][kio]

    // load + split E (64x16 fp32)
    {
        int r = t >> 2, q4 = (t & 3) * 4;
        float4 v = *reinterpret_cast<const float4*>(&E[(n0 + r) * EMB + q4]);
        __nv_bfloat162 h0, l0, h1, l1;
        split_pair(v.x, v.y, h0, l0);
        split_pair(v.z, v.w, h1, l1);
        *reinterpret_cast<__nv_bfloat162*>(&Ah[r][q4]) = h0;
        *reinterpret_cast<__nv_bfloat162*>(&Ah[r][q4 + 2]) = h1;
        *reinterpret_cast<__nv_bfloat162*>(&Al[r][q4]) = l0;
        *reinterpret_cast<__nv_bfloat162*>(&Al[r][q4 + 2]) = l1;
    }
    // load + split Wp (16x256 fp32)
#pragma unroll
    for (int l = 0; l < 4; l++) {
        int idx = t + l * 256;                 // 1024 float4s
        int r = idx >> 6, c4 = (idx & 63) * 4;
        float4 v = *reinterpret_cast<const float4*>(&Wp[(size_t)r * KIO + kio0 + c4]);
        __nv_bfloat162 h0, l0, h1, l1;
        split_pair(v.x, v.y, h0, l0);
        split_pair(v.z, v.w, h1, l1);
        *reinterpret_cast<__nv_bfloat162*>(&Bh[r][c4]) = h0;
        *reinterpret_cast<__nv_bfloat162*>(&Bh[r][c4 + 2]) = h1;
        *reinterpret_cast<__nv_bfloat162*>(&Bl[r][c4]) = l0;
        *reinterpret_cast<__nv_bfloat162*>(&Bl[r][c4 + 2]) = l1;
    }
    __syncthreads();

    // B fragments for this warp's 32 columns
    unsigned Bfh[4][2], Bfl[4][2];
#pragma unroll
    for (int nb = 0; nb < 2; nb++) {
        unsigned tmp[4];
        ldsm_x4_t(tmp, s2u(&Bh[lrow][warp * 32 + nb * 16 + lcol]));
        Bfh[nb * 2][0] = tmp[0]; Bfh[nb * 2][1] = tmp[1];
        Bfh[nb * 2 + 1][0] = tmp[2]; Bfh[nb * 2 + 1][1] = tmp[3];
        ldsm_x4_t(tmp, s2u(&Bl[lrow][warp * 32 + nb * 16 + lcol]));
        Bfl[nb * 2][0] = tmp[0]; Bfl[nb * 2][1] = tmp[1];
        Bfl[nb * 2 + 1][0] = tmp[2]; Bfl[nb * 2 + 1][1] = tmp[3];
    }

    float acc[4][4][4] = {};
#pragma unroll
    for (int mf = 0; mf < 4; mf++) {
        unsigned A_h[4], A_l[4];
        ldsm_x4(A_h, s2u(&Ah[mf * 16 + lrow][lcol]));
        ldsm_x4(A_l, s2u(&Al[mf * 16 + lrow][lcol]));
#pragma unroll
        for (int f = 0; f < 4; f++) {
            mma16816(acc[mf][f], A_h, Bfh[f][0], Bfh[f][1]);
            mma16816(acc[mf][f], A_h, Bfl[f][0], Bfl[f][1]);
            mma16816(acc[mf][f], A_l, Bfh[f][0], Bfh[f][1]);
        }
    }

#pragma unroll
    for (int mf = 0; mf < 4; mf++)
#pragma unroll
        for (int f = 0; f < 4; f++)
#pragma unroll
            for (int h = 0; h < 2; h++) {
                int row = n0 + mf * 16 + g + h * 8;
                int col = kio0 + warp * 32 + f * 8 + tg * 2;
                *reinterpret_cast<float2*>(&g_w[(size_t)row * KIO + col]) =
                    make_float2(acc[mf][f][h * 2], acc[mf][f][h * 2 + 1]);
            }
}

// K1b: bias[n,o] = sum_d E[n,d] * bp[d,o]
__global__ __launch_bounds__(256) void bias_kernel(const float* __restrict__ E,
                                                   const float* __restrict__ bp) {
    int idx = blockIdx.x * 256 + threadIdx.x;       // 65536
    int n = idx >> 6, o = idx & 63;
    float acc = 0.f;
#pragma unroll
    for (int d = 0; d < EMB; d++) acc += E[n * EMB + d] * bp[d * DOUT + o];
    g_bias[idx] = acc;
}

// ---------------------------------------------------------------------------
// K2: e[b,i,j] = exp(-sum_d |pa[b,i,d]-pa[b,j,d]|) -> bf16 hi/lo, packed stores.
// CANONICAL upper-tri tiles only — no transposed copy (consumer reads via
// ldmatrix.trans). Row/col partial sums still emitted.
// ---------------------------------------------------------------------------
__global__ __launch_bounds__(256) void e_kernel(const float* __restrict__ pa) {
    const int b = blockIdx.y;
    int rem = blockIdx.x, ti = 0;
    while (rem >= 16 - ti) { rem -= 16 - ti; ti++; }
    const int tjt = ti + rem;
    const int i0 = ti * 64, j0 = tjt * 64;
    const int t = threadIdx.x;
    const int cp = t & 31, rg = t >> 5;
    const int c0 = cp * 2;

    __shared__ float paI[64][20];
    __shared__ float paJ[64][20];
    __shared__ float vS[64][65];
    __shared__ float cpS[8][64];
    __shared__ float rpS[4][64];

    const float* paB = pa + (size_t)b * NN * DPE;
    {
        int r = t >> 2, q4 = (t & 3) * 4;
        *reinterpret_cast<float4*>(&paI[r][q4]) =
            *reinterpret_cast<const float4*>(&paB[(i0 + r) * DPE + q4]);
        *reinterpret_cast<float4*>(&paJ[r][q4]) =
            *reinterpret_cast<const float4*>(&paB[(j0 + r) * DPE + q4]);
    }
    __syncthreads();

    float pj0[16], pj1[16];
#pragma unroll
    for (int q = 0; q < 4; q++) {
        float4 u = *reinterpret_cast<const float4*>(&paJ[c0][q * 4]);
        pj0[q * 4 + 0] = u.x; pj0[q * 4 + 1] = u.y; pj0[q * 4 + 2] = u.z; pj0[q * 4 + 3] = u.w;
        float4 w = *reinterpret_cast<const float4*>(&paJ[c0 + 1][q * 4]);
        pj1[q * 4 + 0] = w.x; pj1[q * 4 + 1] = w.y; pj1[q * 4 + 2] = w.z; pj1[q * 4 + 3] = w.w;
    }

    const unsigned baseD = (unsigned)((b * NN + i0) * NN + j0);
    float cps0 = 0.f, cps1 = 0.f;
#pragma unroll
    for (int s = 0; s < 8; s++) {
        int i = rg * 8 + s;
        float4 p0 = *reinterpret_cast<const float4*>(&paI[i][0]);
        float4 p1 = *reinterpret_cast<const float4*>(&paI[i][4]);
        float4 p2 = *reinterpret_cast<const float4*>(&paI[i][8]);
        float4 p3 = *reinterpret_cast<const float4*>(&paI[i][12]);
        float d0 = (((fabsf(p0.x - pj0[0])  + fabsf(p0.y - pj0[1]))
                  +  (fabsf(p0.z - pj0[2])  + fabsf(p0.w - pj0[3])))
                 +  ((fabsf(p1.x - pj0[4])  + fabsf(p1.y - pj0[5]))
                  +  (fabsf(p1.z - pj0[6])  + fabsf(p1.w - pj0[7]))))
                 + (((fabsf(p2.x - pj0[8])  + fabsf(p2.y - pj0[9]))
                  +  (fabsf(p2.z - pj0[10]) + fabsf(p2.w - pj0[11])))
                 +  ((fabsf(p3.x - pj0[12]) + fabsf(p3.y - pj0[13]))
                  +  (fabsf(p3.z - pj0[14]) + fabsf(p3.w - pj0[15]))));
        float d1 = (((fabsf(p0.x - pj1[0])  + fabsf(p0.y - pj1[1]))
                  +  (fabsf(p0.z - pj1[2])  + fabsf(p0.w - pj1[3])))
                 +  ((fabsf(p1.x - pj1[4])  + fabsf(p1.y - pj1[5]))
                  +  (fabsf(p1.z - pj1[6])  + fabsf(p1.w - pj1[7]))))
                 + (((fabsf(p2.x - pj1[8])  + fabsf(p2.y - pj1[9]))
                  +  (fabsf(p2.z - pj1[10]) + fabsf(p2.w - pj1[11])))
                 +  ((fabsf(p3.x - pj1[12]) + fabsf(p3.y - pj1[13]))
                  +  (fabsf(p3.z - pj1[14]) + fabsf(p3.w - pj1[15]))));
        float v0 = fexp_neg(d0), v1 = fexp_neg(d1);
        vS[i][c0] = v0; vS[i][c0 + 1] = v1;
        cps0 += v0; cps1 += v1;
        __nv_bfloat162 hv, lv; split_pair(v0, v1, hv, lv);
        unsigned off = baseD + (unsigned)i * NN + c0;
        *reinterpret_cast<__nv_bfloat162*>(g_e_hi + off) = hv;
        *reinterpret_cast<__nv_bfloat162*>(g_e_lo + off) = lv;
    }
    cpS[rg][c0] = cps0; cpS[rg][c0 + 1] = cps1;
    __syncthreads();

    {
        int r = t & 63, qq = t >> 6;
        float s = 0.f;
#pragma unroll
        for (int c = 0; c < 16; c++) s += vS[r][qq * 16 + c];
        rpS[qq][r] = s;
    }
    __syncthreads();

    if (t < 64) {
        float rowP = rpS[0][t] + rpS[1][t] + rpS[2][t] + rpS[3][t];
        g_part[((size_t)b * NN + i0 + t) * 16 + tjt] = rowP;
    } else if (t < 128 && ti != tjt) {
        int c = t - 64;
        float colP = 0.f;
#pragma unroll
        for (int q = 0; q < 8; q++) colP += cpS[q][c];
        g_part[((size_t)b * NN + j0 + c) * 16 + ti] = colP;
    }
}

// ---------------------------------------------------------------------------
// K3: merged Sinv + xs:  xs[row,d] = x[row,d] / sum_k part[row][k]
// ---------------------------------------------------------------------------
__global__ __launch_bounds__(256) void sinv_xs_kernel(const float* __restrict__ x) {
    const int row0 = blockIdx.x * 16;
    const int t = threadIdx.x;
    __shared__ float sInv[16];
    if (t < 16) {
        const float* p = g_part + (size_t)(row0 + t) * 16;
        float s = 0.f;
#pragma unroll
        for (int k = 0; k < 16; k++) s += p[k];
        sInv[t] = 1.0f / s;
    }
    __syncthreads();
    const int rloc = t >> 4, d4 = (t & 15) * 4;
    const size_t row = row0 + rloc;
    float4 v = *reinterpret_cast<const float4*>(&x[row * DIN + d4]);
    float s = sInv[rloc];
    v.x *= s; v.y *= s; v.z *= s; v.w *= s;
    __nv_bfloat162 h0, l0, h1, l1;
    split_pair(v.x, v.y, h0, l0);
    split_pair(v.z, v.w, h1, l1);
    *reinterpret_cast<__nv_bfloat162*>(&g_xs_hi[row * DIN + d4]) = h0;
    *reinterpret_cast<__nv_bfloat162*>(&g_xs_hi[row * DIN + d4 + 2]) = h1;
    *reinterpret_cast<__nv_bfloat162*>(&g_xs_lo[row * DIN + d4]) = l0;
    *reinterpret_cast<__nv_bfloat162*>(&g_xs_lo[row * DIN + d4 + 2]) = l1;
}

// ---------------------------------------------------------------------------
// K4: sxT[m][b][d] = sum_c e[b,m,c] * xs[b,c,d]  via bf16 mma (3-pass split)
// Split-K (2 warpgroups, BK=64), 2-stage cp.async.
// e is stored canonically (upper-tri): K-chunk 'it' < m-tile reads the
// symmetric block [c][m] and uses ldmatrix.trans for A fragments.
// grid (16 m-tiles, 8 b)
// ---------------------------------------------------------------------------
__global__ __launch_bounds__(256) void sx_mma_kernel() {
    const int b = blockIdx.y, mt = blockIdx.x, m0 = mt * 64;
    const int t = threadIdx.x;
    const int warp = t >> 5, lane = t & 31;
    const int wg = warp >> 2, w4 = warp & 3;
    const int g = lane >> 2, tg = lane & 3;

    __shared__ __nv_bfloat16 Ah[2][64][72], Al[2][64][72];
    __shared__ __nv_bfloat16 Bh[2][64][72], Bl[2][64][72];
    __shared__ float redS[4][16][64];

    const __nv_bfloat16* eHiB = g_e_hi + (size_t)b * NN * NN;
    const __nv_bfloat16* eLoB = g_e_lo + (size_t)b * NN * NN;
    const __nv_bfloat16* xHi = g_xs_hi + (size_t)b * NN * DIN;
    const __nv_bfloat16* xLo = g_xs_lo + (size_t)b * NN * DIN;

    float acc[8][4] = {};
    const int lrow = lane & 15;
    const int lcol = (lane & 16) >> 1;
    const int trow = ((lane & 16) >> 1) | (lane & 7);   // trans ldsm row
    const int tcol = lane & 8;                          // trans ldsm col

    auto issue = [&](int st, int chunk) {
        int c0 = chunk * 64;
        bool tr = (chunk < mt);
#pragma unroll
        for (int l = 0; l < 2; l++) {
            int idx = t + l * 256;                   // 512: 64 rows x 8 quads
            int r = idx >> 3, q = (idx & 7) * 8;
            // normal: rows are m (tile (mt, chunk), mt<=chunk)
            // trans:  rows are c (tile (chunk, mt), chunk<mt), cols are m
            size_t src = tr ? ((size_t)(c0 + r) * NN + m0 + q)
                            : ((size_t)(m0 + r) * NN + c0 + q);
            cpa16(&Ah[st][r][q], eHiB + src);
            cpa16(&Al[st][r][q], eLoB + src);
        }
#pragma unroll
        for (int l = 0; l < 2; l++) {
            int idx = t + l * 256;
            int r = idx >> 3, q = (idx & 7) * 8;
            cpa16(&Bh[st][r][q], &xHi[(size_t)(c0 + r) * DIN + q]);
            cpa16(&Bl[st][r][q], &xLo[(size_t)(c0 + r) * DIN + q]);
        }
    };

    issue(0, 0); CP_COMMIT();
    for (int it = 0; it < 16; it++) {
        int cur = it & 1;
        if (it < 15) { issue(cur ^ 1, it + 1); CP_COMMIT(); CP_WAIT1(); }
        else CP_WAIT0();
        __syncthreads();
        const bool tr = (it < mt);

#pragma unroll
        for (int k16 = 0; k16 < 2; k16++) {
            int kk = wg * 2 + k16;
            unsigned A_h[4], A_l[4];
            if (tr) {
                ldsm_x4_t(A_h, s2u(&Ah[cur][kk * 16 + trow][w4 * 16 + tcol]));
                ldsm_x4_t(A_l, s2u(&Al[cur][kk * 16 + trow][w4 * 16 + tcol]));
            } else {
                ldsm_x4(A_h, s2u(&Ah[cur][w4 * 16 + lrow][kk * 16 + lcol]));
                ldsm_x4(A_l, s2u(&Al[cur][w4 * 16 + lrow][kk * 16 + lcol]));
            }
            unsigned Bfh[8][2], Bfl[8][2];
#pragma unroll
            for (int nb = 0; nb < 4; nb++) {
                unsigned tmp[4];
                ldsm_x4_t(tmp, s2u(&Bh[cur][kk * 16 + lrow][nb * 16 + lcol]));
                Bfh[nb * 2][0] = tmp[0]; Bfh[nb * 2][1] = tmp[1];
                Bfh[nb * 2 + 1][0] = tmp[2]; Bfh[nb * 2 + 1][1] = tmp[3];
                ldsm_x4_t(tmp, s2u(&Bl[cur][kk * 16 + lrow][nb * 16 + lcol]));
                Bfl[nb * 2][0] = tmp[0]; Bfl[nb * 2][1] = tmp[1];
                Bfl[nb * 2 + 1][0] = tmp[2]; Bfl[nb * 2 + 1][1] = tmp[3];
            }
#pragma unroll
            for (int f = 0; f < 8; f++) {
                mma16816(acc[f], A_h, Bfh[f][0], Bfh[f][1]);
                mma16816(acc[f], A_h, Bfl[f][0], Bfl[f][1]);
                mma16816(acc[f], A_l, Bfh[f][0], Bfh[f][1]);
            }
        }
        __syncthreads();
    }

    if (wg == 1) {
#pragma unroll
        for (int f = 0; f < 8; f++)
#pragma unroll
            for (int h = 0; h < 2; h++)
                *reinterpret_cast<float2*>(&redS[w4][g + h * 8][f * 8 + tg * 2]) =
                    make_float2(acc[f][h * 2], acc[f][h * 2 + 1]);
    }
    __syncthreads();
    if (wg == 0) {
        const int m_lo = m0 + w4 * 16 + g;
#pragma unroll
        for (int f = 0; f < 8; f++) {
            int col = f * 8 + tg * 2;
#pragma unroll
            for (int h = 0; h < 2; h++) {
                float2 r = *reinterpret_cast<const float2*>(&redS[w4][g + h * 8][col]);
                float vx = acc[f][h * 2] + r.x, vy = acc[f][h * 2 + 1] + r.y;
                int m = m_lo + h * 8;
                size_t o = ((size_t)m * BB + b) * DIN + col;
                *reinterpret_cast<float2*>(&g_sxT[o]) = make_float2(vx, vy);
                __nv_bfloat162 hv, lv; split_pair(vx, vy, hv, lv);
                *reinterpret_cast<__nv_bfloat162*>(&g_sxT_hi[o]) = hv;
                *reinterpret_cast<__nv_bfloat162*>(&g_sxT_lo[o]) = lv;
            }
        }
    }
}

// ---------------------------------------------------------------------------
// K5: s1[n][bd] = sum_m sim[n,m] * sxT[m][bd]  — split-K scheme (sim NOT
// symmetric: plain path).  grid (16 n-tiles, 8 bd-tiles)
// ---------------------------------------------------------------------------
__global__ __launch_bounds__(256) void s1_mma_kernel() {
    const int n0 = blockIdx.x * 64, bd0 = blockIdx.y * 64;
    const int t = threadIdx.x;
    const int warp = t >> 5, lane = t & 31;
    const int wg = warp >> 2, w4 = warp & 3;
    const int g = lane >> 2, tg = lane & 3;

    __shared__ __nv_bfloat16 Ah[2][64][72], Al[2][64][72];
    __shared__ __nv_bfloat16 Bh[2][64][72], Bl[2][64][72];
    __shared__ float redS[4][16][64];

    const __nv_bfloat16* aHi = g_sim_hi + (size_t)n0 * NN;
    const __nv_bfloat16* aLo = g_sim_lo + (size_t)n0 * NN;

    float acc[8][4] = {};
    const int lrow = lane & 15;
    const int lcol = (lane & 16) >> 1;

    auto issue = [&](int st, int c0) {
#pragma unroll
        for (int l = 0; l < 2; l++) {
            int idx = t + l * 256;
            int r = idx >> 3, q = (idx & 7) * 8;
            cpa16(&Ah[st][r][q], &aHi[(size_t)r * NN + c0 + q]);
            cpa16(&Al[st][r][q], &aLo[(size_t)r * NN + c0 + q]);
        }
#pragma unroll
        for (int l = 0; l < 2; l++) {
            int idx = t + l * 256;
            int r = idx >> 3, q = (idx & 7) * 8;
            cpa16(&Bh[st][r][q], &g_sxT_hi[(size_t)(c0 + r) * (BB * DIN) + bd0 + q]);
            cpa16(&Bl[st][r][q], &g_sxT_lo[(size_t)(c0 + r) * (BB * DIN) + bd0 + q]);
        }
    };

    issue(0, 0); CP_COMMIT();
    for (int it = 0; it < 16; it++) {
        int cur = it & 1;
        if (it < 15) { issue(cur ^ 1, (it + 1) * 64); CP_COMMIT(); CP_WAIT1(); }
        else CP_WAIT0();
        __syncthreads();

#pragma unroll
        for (int k16 = 0; k16 < 2; k16++) {
            int kk = wg * 2 + k16;
            unsigned A_h[4], A_l[4];
            ldsm_x4(A_h, s2u(&Ah[cur][w4 * 16 + lrow][kk * 16 + lcol]));
            ldsm_x4(A_l, s2u(&Al[cur][w4 * 16 + lrow][kk * 16 + lcol]));
            unsigned Bfh[8][2], Bfl[8][2];
#pragma unroll
            for (int nb = 0; nb < 4; nb++) {
                unsigned tmp[4];
                ldsm_x4_t(tmp, s2u(&Bh[cur][kk * 16 + lrow][nb * 16 + lcol]));
                Bfh[nb * 2][0] = tmp[0]; Bfh[nb * 2][1] = tmp[1];
                Bfh[nb * 2 + 1][0] = tmp[2]; Bfh[nb * 2 + 1][1] = tmp[3];
                ldsm_x4_t(tmp, s2u(&Bl[cur][kk * 16 + lrow][nb * 16 + lcol]));
                Bfl[nb * 2][0] = tmp[0]; Bfl[nb * 2][1] = tmp[1];
                Bfl[nb * 2 + 1][0] = tmp[2]; Bfl[nb * 2 + 1][1] = tmp[3];
            }
#pragma unroll
            for (int f = 0; f < 8; f++) {
                mma16816(acc[f], A_h, Bfh[f][0], Bfh[f][1]);
                mma16816(acc[f], A_h, Bfl[f][0], Bfl[f][1]);
                mma16816(acc[f], A_l, Bfh[f][0], Bfh[f][1]);
            }
        }
        __syncthreads();
    }

    if (wg == 1) {
#pragma unroll
        for (int f = 0; f < 8; f++)
#pragma unroll
            for (int h = 0; h < 2; h++)
                *reinterpret_cast<float2*>(&redS[w4][g + h * 8][f * 8 + tg * 2]) =
                    make_float2(acc[f][h * 2], acc[f][h * 2 + 1]);
    }
    __syncthreads();
    if (wg == 0) {
        const int n_lo = n0 + w4 * 16 + g;
#pragma unroll
        for (int f = 0; f < 8; f++) {
            int col = f * 8 + tg * 2;
#pragma unroll
            for (int h = 0; h < 2; h++) {
                float2 r = *reinterpret_cast<const float2*>(&redS[w4][g + h * 8][col]);
                int n = n_lo + h * 8;
                *reinterpret_cast<float2*>(&g_s1[(size_t)n * (BB * DIN) + bd0 + col]) =
                    make_float2(acc[f][h * 2] + r.x, acc[f][h * 2 + 1] + r.y);
            }
        }
    }
}

// ---------------------------------------------------------------------------
// K6: out[b,n,o] = bias[n,o] + sum_{k,i} xg[k][n,b,i] w[n,k,i,o]
// ---------------------------------------------------------------------------
__global__ __launch_bounds__(128) void out_kernel(float* __restrict__ out) {
    const int n = blockIdx.x, t = threadIdx.x;
    __shared__ float wS[KIO];
    __shared__ float xgS[2][BB][DIN];
    __shared__ float bSh[DOUT];
    __shared__ float red[8][BB][68];
    const float* wp = g_w + (size_t)n * KIO;
#pragma unroll
    for (int l = 0; l < 16; l++) {
        int idx4 = t + l * 128;
        *reinterpret_cast<float4*>(&wS[idx4 * 4]) =
            *reinterpret_cast<const float4*>(&wp[idx4 * 4]);
    }
#pragma unroll
    for (int l = 0; l < 2; l++) {
        int idx4 = t + l * 128;
        float* xgFlat = &xgS[0][0][0];
        const float* src = (idx4 < 128) ? (g_sxT + (size_t)n * (BB * DIN) + idx4 * 4)
                                        : (g_s1  + (size_t)n * (BB * DIN) + (idx4 - 128) * 4);
        *reinterpret_cast<float4*>(&xgFlat[idx4 * 4]) =
            *reinterpret_cast<const float4*>(src);
    }
    if (t < DOUT) bSh[t] = g_bias[n * DOUT + t];
    __syncthreads();

    const int sp = t >> 4;
    const int og = t & 15;
    const int o4 = og * 4;
    float acc[BB][4] = {};
#pragma unroll
    for (int ii = 0; ii < 16; ii++) {
        int ki = sp * 16 + ii;
        int k = ki >> 6, i = ki & 63;
        float4 wv = *reinterpret_cast<const float4*>(&wS[ki * 64 + o4]);
#pragma unroll
        for (int b = 0; b < BB; b++) {
            float xv = xgS[k][b][i];
            acc[b][0] += xv * wv.x;
            acc[b][1] += xv * wv.y;
            acc[b][2] += xv * wv.z;
            acc[b][3] += xv * wv.w;
        }
    }
#pragma unroll
    for (int b = 0; b < BB; b++)
        *reinterpret_cast<float4*>(&red[sp][b][o4]) =
            make_float4(acc[b][0], acc[b][1], acc[b][2], acc[b][3]);
    __syncthreads();

    {
        const int b = t >> 4, o4e = (t & 15) * 4;
        float4 r = make_float4(bSh[o4e], bSh[o4e + 1], bSh[o4e + 2], bSh[o4e + 3]);
#pragma unroll
        for (int s = 0; s < 8; s++) {
            float4 p = *reinterpret_cast<const float4*>(&red[s][b][o4e]);
            r.x += p.x; r.y += p.y; r.z += p.z; r.w += p.w;
        }
        *reinterpret_cast<float4*>(&out[((size_t)b * NN + n) * DOUT + o4e]) = r;
    }
}

// ---------------------------------------------------------------------------
extern "C" void kernel_launch(void* const* d_in, const int* in_sizes, int n_in,
                              void* d_out, int out_size) {
    const float* x    = (const float*)d_in[0];   // [8,1024,64]
    const float* E    = (const float*)d_in[1];   // [1024,16]
    const float* pa   = (const float*)d_in[2];   // [8,1024,16]
    const float* Wp   = (const float*)d_in[3];   // [16,2,64,64]
    const float* bp   = (const float*)d_in[4];   // [16,64]
    float* out = (float*)d_out;                  // [8,1024,64]

    sim_kernel<<<NN, 256>>>(E);
    weights_mma_kernel<<<dim3(KIO / 256, NN / 64), 256>>>(E, Wp);
    bias_kernel<<<NN * DOUT / 256, 256>>>(E, bp);
    e_kernel<<<dim3(136, BB), 256>>>(pa);
    sinv_xs_kernel<<<BB * NN / 16, 256>>>(x);
    sx_mma_kernel<<<dim3(NN / 64, BB), 256>>>();
    s1_mma_kernel<<<dim3(NN / 64, BB * DIN / 64), 256>>>();
    out_kernel<<<NN, 128>>>(out);
}